// round 8
// baseline (speedup 1.0000x reference)
#include <cuda_runtime.h>
#include <math.h>
#include <stdint.h>

#define T_   512
#define B_   128
#define E_   128
#define HD_  128
#define G4_  512   // 4*HD
#define K_   9
#define V_   50000

// ---------------- scratch (device globals; no runtime allocation) -------------
__device__ float  g_Xf[(size_t)T_ * B_ * G4_];   // [t][b][512] fwd input proj + bias
__device__ float  g_Xb[(size_t)T_ * B_ * G4_];   // backward
__device__ float  g_H [(size_t)T_ * B_ * 256];   // [t][b][256] concat hidden
__device__ float  g_emis[(size_t)B_ * T_ * K_];  // [b][t][k]
__device__ float4 g_WT[2 * 32 * 512];            // [dir][k4][r] packed W_hh rows

// ---------------- kernel 0: pack W_hh into k-major float4 ---------------------
__global__ void wtrans_kernel(const float* __restrict__ wf, const float* __restrict__ wb)
{
    int idx = blockIdx.x * 256 + threadIdx.x;          // 0..32767
    int dir = idx >> 14;
    int rem = idx & 16383;
    int k4  = rem >> 9;
    int r   = rem & 511;
    const float* w = dir ? wb : wf;
    const float* p = &w[(size_t)r * HD_ + 4 * k4];
    g_WT[idx] = make_float4(p[0], p[1], p[2], p[3]);
}

// ---------------- kernel A: embed gather + input projection GEMM --------------
// C[65536,1024] = gather(emb,x) @ [w_ih_f.T | w_ih_b.T] + (b_ih+b_hh)
__global__ void proj_kernel(const int* __restrict__ x, const float* __restrict__ emb,
                            const float* __restrict__ w_f, const float* __restrict__ w_b,
                            const float* __restrict__ bihf, const float* __restrict__ bhhf,
                            const float* __restrict__ bihb, const float* __restrict__ bhhb)
{
    __shared__ float As[64][65];
    __shared__ float Bs[64][65];
    __shared__ float bias_s[64];
    __shared__ int   tok_s[64];

    const int tid = threadIdx.x;
    const int m0 = blockIdx.y * 64;
    const int n0 = blockIdx.x * 64;           // 0..1023
    const int dir = n0 >> 9;
    const int gbase = n0 & 511;
    const float* w  = dir ? w_b  : w_f;
    const float* bi = dir ? bihb : bihf;
    const float* bh = dir ? bhhb : bhhf;

    if (tid < 64) {
        int m = m0 + tid;
        int t = m >> 7, b = m & 127;
        int tok = x[b * T_ + t];
        if ((unsigned)tok >= (unsigned)V_) tok = 0;   // safety clamp
        tok_s[tid] = tok;
        int grow = gbase + tid;
        bias_s[tid] = bi[grow] + bh[grow];
    }
    __syncthreads();

    const int tx = tid & 15, ty = tid >> 4;
    float acc[4][4];
#pragma unroll
    for (int i = 0; i < 4; i++)
#pragma unroll
        for (int j = 0; j < 4; j++) acc[i][j] = 0.f;

    for (int kc = 0; kc < 128; kc += 64) {
        __syncthreads();
        for (int idx = tid; idx < 4096; idx += 256) {
            int row = idx >> 6, kk = idx & 63;
            As[row][kk] = emb[(size_t)tok_s[row] * E_ + kc + kk];
            Bs[row][kk] = w[(size_t)(gbase + row) * E_ + kc + kk];
        }
        __syncthreads();

#pragma unroll 8
        for (int k = 0; k < 64; k++) {
            float a[4], bb[4];
#pragma unroll
            for (int i = 0; i < 4; i++) a[i] = As[ty + 16 * i][k];
#pragma unroll
            for (int j = 0; j < 4; j++) bb[j] = Bs[tx + 16 * j][k];
#pragma unroll
            for (int i = 0; i < 4; i++)
#pragma unroll
                for (int j = 0; j < 4; j++) acc[i][j] += a[i] * bb[j];
        }
    }

    float* X = dir ? g_Xb : g_Xf;
#pragma unroll
    for (int i = 0; i < 4; i++) {
        int m = m0 + ty + 16 * i;
#pragma unroll
        for (int j = 0; j < 4; j++) {
            int col = tx + 16 * j;
            X[(size_t)m * G4_ + gbase + col] = acc[i][j] + bias_s[col];
        }
    }
}

// ---------------- kernel B: batch-split LSTM, zero inter-CTA communication ----
__global__ void lstm_kernel()
{
    __shared__ __align__(16) float h_s[4 * HD_];   // [b][k]
    __shared__ float gates_s[4 * G4_];             // [b][r]  8KB

    const int tid = threadIdx.x;
    const int dir = blockIdx.x >> 5;
    const int b0  = (blockIdx.x & 31) * 4;

    const float*  Xin = dir ? g_Xb : g_Xf;
    const float4* WT  = &g_WT[dir * 16384];

    if (tid < 4 * HD_) h_s[tid] = 0.f;
    const int r = tid;              // GEMM role: gate row 0..511
    const int ba = tid >> 7;        // ACT role: batch 0..3
    const int u  = tid & 127;       // ACT role: hidden unit
    float c = 0.f;
    const float4* h4 = (const float4*)h_s;
    __syncthreads();

    for (int s = 0; s < T_; s++) {
        const int t = dir ? (T_ - 1 - s) : s;

        const float* Xr = &Xin[(size_t)t * B_ * G4_ + (size_t)(b0 + ba) * G4_];
        float x0 = Xr[u], x1 = Xr[128 + u], x2 = Xr[256 + u], x3 = Xr[384 + u];

        float a0 = 0.f, a1 = 0.f, a2 = 0.f, a3 = 0.f;
#pragma unroll 8
        for (int k4 = 0; k4 < 32; k4++) {
            float4 w  = WT[k4 * 512 + r];
            float4 h0 = h4[0 * 32 + k4];
            float4 h1 = h4[1 * 32 + k4];
            float4 h2 = h4[2 * 32 + k4];
            float4 h3 = h4[3 * 32 + k4];
            a0 += w.x * h0.x + w.y * h0.y + w.z * h0.z + w.w * h0.w;
            a1 += w.x * h1.x + w.y * h1.y + w.z * h1.z + w.w * h1.w;
            a2 += w.x * h2.x + w.y * h2.y + w.z * h2.z + w.w * h2.w;
            a3 += w.x * h3.x + w.y * h3.y + w.z * h3.z + w.w * h3.w;
        }
        gates_s[0 * G4_ + r] = a0;
        gates_s[1 * G4_ + r] = a1;
        gates_s[2 * G4_ + r] = a2;
        gates_s[3 * G4_ + r] = a3;
        __syncthreads();

        float pi = gates_s[ba * G4_ +       u] + x0;
        float pf = gates_s[ba * G4_ + 128 + u] + x1;
        float pg = gates_s[ba * G4_ + 256 + u] + x2;
        float po = gates_s[ba * G4_ + 384 + u] + x3;
        float ig = 1.f / (1.f + expf(-pi));
        float fg = 1.f / (1.f + expf(-pf));
        float gg = tanhf(pg);
        float og = 1.f / (1.f + expf(-po));
        c = fg * c + ig * gg;
        float h = og * tanhf(c);

        h_s[ba * HD_ + u] = h;
        g_H[(size_t)t * B_ * 256 + (size_t)(b0 + ba) * 256 + dir * 128 + u] = h;
        __syncthreads();
    }
}

// ---------------- kernel C: emissions = H @ W_tag.T + b_tag -------------------
__global__ void emis_kernel(const float* __restrict__ W_tag, const float* __restrict__ b_tag)
{
    __shared__ float Ws[K_ * 256];
    __shared__ float bs[K_];
    const int tid = threadIdx.x;
    for (int i = tid; i < K_ * 256; i += 256) Ws[i] = W_tag[i];
    if (tid < K_) bs[tid] = b_tag[tid];
    __syncthreads();

    const int warp = tid >> 5, lane = tid & 31;
    const int rr = blockIdx.x * 8 + warp;          // row in [t*128+b]
    const float* hrow = &g_H[(size_t)rr * 256];
    float hv[8];
#pragma unroll
    for (int i = 0; i < 8; i++) hv[i] = hrow[lane + 32 * i];
    const int t = rr >> 7, b = rr & 127;
#pragma unroll
    for (int k = 0; k < K_; k++) {
        float s = 0.f;
#pragma unroll
        for (int i = 0; i < 8; i++) s += hv[i] * Ws[k * 256 + lane + 32 * i];
#pragma unroll
        for (int off = 16; off > 0; off >>= 1) s += __shfl_down_sync(0xffffffffu, s, off);
        if (lane == 0) g_emis[(size_t)b * T_ * K_ + t * K_ + k] = s + bs[k];
    }
}

// ---------------- kernel D: CRF Viterbi — one warp per batch ------------------
// Output written as FLOAT32 (the harness compares the output buffer as f32;
// integer bit patterns read as denormals ~0 -> the constant rel_err=1.0 we saw).
__global__ void viterbi_kernel(const float* __restrict__ start_t, const float* __restrict__ end_t,
                               const float* __restrict__ trans, float* __restrict__ out)
{
    __shared__ unsigned char bp[4][T_ * K_];   // 18432 bytes
    const int tid = threadIdx.x, warp = tid >> 5, lane = tid & 31;
    const int b = blockIdx.x * 4 + warp;

    const float* emp = &g_emis[(size_t)b * T_ * K_];
    const bool act = (lane < K_);

    float tr[K_];
    float score;
    if (act) {
#pragma unroll
        for (int i = 0; i < K_; i++) tr[i] = trans[i * K_ + lane];
        score = start_t[lane] + __ldg(&emp[lane]);
    } else {
#pragma unroll
        for (int i = 0; i < K_; i++) tr[i] = 0.f;
        score = -3.0e38f;
    }
    __syncwarp();

    for (int t = 1; t < T_; t++) {
        float em_t = act ? __ldg(&emp[t * K_ + lane]) : 0.f;
        float m = -3.0e38f; int arg = 0;
#pragma unroll
        for (int i = 0; i < K_; i++) {
            float si = __shfl_sync(0xffffffffu, score, i);
            float v = si + tr[i];
            if (v > m) { m = v; arg = i; }   // strict > keeps first max (jnp.argmax)
        }
        if (act) {
            bp[warp][t * K_ + lane] = (unsigned char)arg;
            score = m + em_t;
        }
    }
    if (act) score += end_t[lane];

    int best = 0; float bm = -3.0e38f;
#pragma unroll
    for (int jj = 0; jj < K_; jj++) {
        float sj = __shfl_sync(0xffffffffu, score, jj);
        if (sj > bm) { bm = sj; best = jj; }
    }
    __syncwarp();   // bp[] from lanes 1..8 visible to lane 0
    if (lane == 0) {
        int tag = best;
        out[b * T_ + (T_ - 1)] = (float)tag;
        for (int t = T_ - 2; t >= 0; t--) {
            tag = bp[warp][(t + 1) * K_ + tag];
            out[b * T_ + t] = (float)tag;
        }
    }
}

// ---------------- launch -------------------------------------------------------
extern "C" void kernel_launch(void* const* d_in, const int* in_sizes, int n_in,
                              void* d_out, int out_size)
{
    const int*   x      = (const int*)  d_in[0];
    const float* emb    = (const float*)d_in[1];
    const float* w_ih_f = (const float*)d_in[2];
    const float* w_hh_f = (const float*)d_in[3];
    const float* b_ih_f = (const float*)d_in[4];
    const float* b_hh_f = (const float*)d_in[5];
    const float* w_ih_b = (const float*)d_in[6];
    const float* w_hh_b = (const float*)d_in[7];
    const float* b_ih_b = (const float*)d_in[8];
    const float* b_hh_b = (const float*)d_in[9];
    const float* W_tag  = (const float*)d_in[10];
    const float* b_tag  = (const float*)d_in[11];
    const float* start_t= (const float*)d_in[12];
    const float* end_t  = (const float*)d_in[13];
    const float* trans  = (const float*)d_in[14];
    float* out = (float*)d_out;

    wtrans_kernel<<<128, 256>>>(w_hh_f, w_hh_b);
    proj_kernel<<<dim3(16, 1024), 256>>>(x, emb, w_ih_f, w_ih_b,
                                         b_ih_f, b_hh_f, b_ih_b, b_hh_b);
    lstm_kernel<<<64, 512>>>();
    emis_kernel<<<8192, 256>>>(W_tag, b_tag);
    viterbi_kernel<<<32, 128>>>(start_t, end_t, trans, out);
}

// round 9
// speedup vs baseline: 1.2378x; 1.2378x over previous
#include <cuda_runtime.h>
#include <math.h>
#include <stdint.h>

#define T_   512
#define B_   128
#define E_   128
#define HD_  128
#define G4_  512   // 4*HD
#define K_   9
#define V_   50000

typedef unsigned long long ull;

// ---------------- f32x2 packed-math helpers (FFMA2 — PTX-only on sm_103a) -----
__device__ __forceinline__ void fma2(ull& d, ull a, ull b) {
    asm("fma.rn.f32x2 %0, %1, %2, %0;" : "+l"(d) : "l"(a), "l"(b));
}
__device__ __forceinline__ ull dup2(float x) {
    ull r;
    asm("mov.b64 %0, {%1, %1};" : "=l"(r) : "f"(x));
    return r;
}
__device__ __forceinline__ float2 unpack2(ull v) {
    float2 f;
    asm("mov.b64 {%0, %1}, %2;" : "=f"(f.x), "=f"(f.y) : "l"(v));
    return f;
}

// ---------------- scratch (device globals; no runtime allocation) -------------
__device__ float  g_Xf[(size_t)T_ * B_ * G4_];   // [t][b][512] fwd input proj + bias
__device__ float  g_Xb[(size_t)T_ * B_ * G4_];   // backward
__device__ float  g_H [(size_t)T_ * B_ * 256];   // [t][b][256] concat hidden
__device__ float  g_emis[(size_t)B_ * T_ * K_];  // [b][t][k]
__device__ float4 g_WT[2 * 32 * 512];            // [dir][k4][r] packed W_hh rows

// ---------------- kernel 0: pack W_hh into k-major float4 ---------------------
__global__ void wtrans_kernel(const float* __restrict__ wf, const float* __restrict__ wb)
{
    int idx = blockIdx.x * 256 + threadIdx.x;          // 0..32767
    int dir = idx >> 14;
    int rem = idx & 16383;
    int k4  = rem >> 9;
    int r   = rem & 511;
    const float* w = dir ? wb : wf;
    const float* p = &w[(size_t)r * HD_ + 4 * k4];
    g_WT[idx] = make_float4(p[0], p[1], p[2], p[3]);
}

// ---------------- kernel A: embed gather + input projection GEMM --------------
// C[65536,1024] = gather(emb,x) @ [w_ih_f.T | w_ih_b.T] + (b_ih+b_hh)
// 64x64 tiles, k-major smem, f32x2 packed accumulation. grid (16,1024), blk 256.
__global__ void proj_kernel(const int* __restrict__ x, const float* __restrict__ emb,
                            const float* __restrict__ w_f, const float* __restrict__ w_b,
                            const float* __restrict__ bihf, const float* __restrict__ bhhf,
                            const float* __restrict__ bihb, const float* __restrict__ bhhb)
{
    __shared__ float As[64][72];      // [k][row], 72-pad keeps 16B row alignment
    __shared__ float Bs[64][72];      // [k][col]
    __shared__ float bias_s[64];
    __shared__ int   tok_s[64];

    const int tid = threadIdx.x;
    const int m0 = blockIdx.y * 64;
    const int n0 = blockIdx.x * 64;           // 0..1023
    const int dir = n0 >> 9;
    const int gbase = n0 & 511;
    const float* w  = dir ? w_b  : w_f;
    const float* bi = dir ? bihb : bihf;
    const float* bh = dir ? bhhb : bhhf;

    if (tid < 64) {
        int m = m0 + tid;
        int t = m >> 7, b = m & 127;
        int tok = x[b * T_ + t];
        if ((unsigned)tok >= (unsigned)V_) tok = 0;   // safety clamp
        tok_s[tid] = tok;
        int grow = gbase + tid;
        bias_s[tid] = bi[grow] + bh[grow];
    }
    __syncthreads();

    const int tx = tid & 15, ty = tid >> 4;   // micro tile: rows ty*4.., cols tx*4..
    ull acc[4][2];
#pragma unroll
    for (int i = 0; i < 4; i++) { acc[i][0] = 0ull; acc[i][1] = 0ull; }

    for (int kc = 0; kc < 128; kc += 64) {
        // fill transposed (k-major); coalesced global reads
        for (int idx = tid; idx < 4096; idx += 256) {
            int row = idx >> 6, kk = idx & 63;
            As[kk][row] = emb[(size_t)tok_s[row] * E_ + kc + kk];
            Bs[kk][row] = w[(size_t)(gbase + row) * E_ + kc + kk];
        }
        __syncthreads();

#pragma unroll 8
        for (int k = 0; k < 64; k++) {
            float4     av = *(const float4*)&As[k][ty * 4];
            ulonglong2 bv = *(const ulonglong2*)&Bs[k][tx * 4];  // 2 packed col-pairs
            ull a0 = dup2(av.x), a1 = dup2(av.y), a2 = dup2(av.z), a3 = dup2(av.w);
            fma2(acc[0][0], a0, bv.x); fma2(acc[0][1], a0, bv.y);
            fma2(acc[1][0], a1, bv.x); fma2(acc[1][1], a1, bv.y);
            fma2(acc[2][0], a2, bv.x); fma2(acc[2][1], a2, bv.y);
            fma2(acc[3][0], a3, bv.x); fma2(acc[3][1], a3, bv.y);
        }
        __syncthreads();
    }

    float* X = dir ? g_Xb : g_Xf;
    const int col = tx * 4;
#pragma unroll
    for (int i = 0; i < 4; i++) {
        int m = m0 + ty * 4 + i;
        float2 c01 = unpack2(acc[i][0]);
        float2 c23 = unpack2(acc[i][1]);
        float4 o = make_float4(c01.x + bias_s[col + 0], c01.y + bias_s[col + 1],
                               c23.x + bias_s[col + 2], c23.y + bias_s[col + 3]);
        *(float4*)&X[(size_t)m * G4_ + gbase + col] = o;
    }
}

// ---------------- kernel B: batch-split LSTM with f32x2 batch-pair GEMM -------
// 64 CTAs: dir = blk>>5, 4 batches each, 512 threads. h stored [k][b] so one
// LDS.128 yields two pre-packed batch pairs. Accumulation order per batch is
// identical to the scalar version (bit-exact).
__global__ void lstm_kernel()
{
    __shared__ __align__(16) float hkb[HD_ * 4];   // [k][b]  2KB
    __shared__ float gates_s[4 * G4_];             // [b][r]  8KB

    const int tid = threadIdx.x;
    const int dir = blockIdx.x >> 5;
    const int b0  = (blockIdx.x & 31) * 4;

    const float*  Xin = dir ? g_Xb : g_Xf;
    const float4* WT  = &g_WT[dir * 16384];

    if (tid < HD_ * 4) hkb[tid] = 0.f;
    const int r  = tid;             // GEMM role: gate row 0..511
    const int ba = tid >> 7;        // ACT role: batch 0..3
    const int u  = tid & 127;       // ACT role: hidden unit
    float c = 0.f;
    __syncthreads();

    for (int s = 0; s < T_; s++) {
        const int t = dir ? (T_ - 1 - s) : s;

        // prefetch X for activation phase (held through GEMM)
        const float* Xr = &Xin[(size_t)t * B_ * G4_ + (size_t)(b0 + ba) * G4_];
        float x0 = Xr[u], x1 = Xr[128 + u], x2 = Xr[256 + u], x3 = Xr[384 + u];

        // gates[b][r] = sum_k h[b][k] * W_hh[r][k]  (pairs: b01, b23)
        ull a01 = 0ull, a23 = 0ull;
#pragma unroll 8
        for (int k4 = 0; k4 < 32; k4++) {
            float4 w4 = WT[k4 * 512 + r];
            ulonglong2 h0 = *(const ulonglong2*)&hkb[(k4 * 4 + 0) * 4];
            ull wd = dup2(w4.x);
            fma2(a01, wd, h0.x); fma2(a23, wd, h0.y);
            ulonglong2 h1 = *(const ulonglong2*)&hkb[(k4 * 4 + 1) * 4];
            wd = dup2(w4.y);
            fma2(a01, wd, h1.x); fma2(a23, wd, h1.y);
            ulonglong2 h2 = *(const ulonglong2*)&hkb[(k4 * 4 + 2) * 4];
            wd = dup2(w4.z);
            fma2(a01, wd, h2.x); fma2(a23, wd, h2.y);
            ulonglong2 h3 = *(const ulonglong2*)&hkb[(k4 * 4 + 3) * 4];
            wd = dup2(w4.w);
            fma2(a01, wd, h3.x); fma2(a23, wd, h3.y);
        }
        {
            float2 g01 = unpack2(a01);
            float2 g23 = unpack2(a23);
            gates_s[0 * G4_ + r] = g01.x;
            gates_s[1 * G4_ + r] = g01.y;
            gates_s[2 * G4_ + r] = g23.x;
            gates_s[3 * G4_ + r] = g23.y;
        }
        __syncthreads();   // gates ready; all h reads done before overwrite

        // activation: thread owns (batch ba, unit u) — identical numerics
        float pi = gates_s[ba * G4_ +       u] + x0;
        float pf = gates_s[ba * G4_ + 128 + u] + x1;
        float pg = gates_s[ba * G4_ + 256 + u] + x2;
        float po = gates_s[ba * G4_ + 384 + u] + x3;
        float ig = 1.f / (1.f + expf(-pi));
        float fg = 1.f / (1.f + expf(-pf));
        float gg = tanhf(pg);
        float og = 1.f / (1.f + expf(-po));
        c = fg * c + ig * gg;
        float h = og * tanhf(c);

        hkb[u * 4 + ba] = h;
        g_H[(size_t)t * B_ * 256 + (size_t)(b0 + ba) * 256 + dir * 128 + u] = h;
        __syncthreads();   // h complete before next step's GEMM
    }
}

// ---------------- kernel C: emissions = H @ W_tag.T + b_tag -------------------
__global__ void emis_kernel(const float* __restrict__ W_tag, const float* __restrict__ b_tag)
{
    __shared__ float Ws[K_ * 256];
    __shared__ float bs[K_];
    const int tid = threadIdx.x;
    for (int i = tid; i < K_ * 256; i += 256) Ws[i] = W_tag[i];
    if (tid < K_) bs[tid] = b_tag[tid];
    __syncthreads();

    const int warp = tid >> 5, lane = tid & 31;
    const int rr = blockIdx.x * 8 + warp;          // row in [t*128+b]
    const float* hrow = &g_H[(size_t)rr * 256];
    float hv[8];
#pragma unroll
    for (int i = 0; i < 8; i++) hv[i] = hrow[lane + 32 * i];
    const int t = rr >> 7, b = rr & 127;
#pragma unroll
    for (int k = 0; k < K_; k++) {
        float s = 0.f;
#pragma unroll
        for (int i = 0; i < 8; i++) s += hv[i] * Ws[k * 256 + lane + 32 * i];
#pragma unroll
        for (int off = 16; off > 0; off >>= 1) s += __shfl_down_sync(0xffffffffu, s, off);
        if (lane == 0) g_emis[(size_t)b * T_ * K_ + t * K_ + k] = s + bs[k];
    }
}

// ---------------- kernel D: CRF Viterbi — one warp per batch ------------------
// Output written as FLOAT32 (harness compares output buffer as f32).
__global__ void viterbi_kernel(const float* __restrict__ start_t, const float* __restrict__ end_t,
                               const float* __restrict__ trans, float* __restrict__ out)
{
    __shared__ unsigned char bp[4][T_ * K_];   // 18432 bytes
    const int tid = threadIdx.x, warp = tid >> 5, lane = tid & 31;
    const int b = blockIdx.x * 4 + warp;

    const float* emp = &g_emis[(size_t)b * T_ * K_];
    const bool act = (lane < K_);

    float tr[K_];
    float score;
    if (act) {
#pragma unroll
        for (int i = 0; i < K_; i++) tr[i] = trans[i * K_ + lane];
        score = start_t[lane] + __ldg(&emp[lane]);
    } else {
#pragma unroll
        for (int i = 0; i < K_; i++) tr[i] = 0.f;
        score = -3.0e38f;
    }
    __syncwarp();

    for (int t = 1; t < T_; t++) {
        float em_t = act ? __ldg(&emp[t * K_ + lane]) : 0.f;
        float m = -3.0e38f; int arg = 0;
#pragma unroll
        for (int i = 0; i < K_; i++) {
            float si = __shfl_sync(0xffffffffu, score, i);
            float v = si + tr[i];
            if (v > m) { m = v; arg = i; }   // strict > keeps first max (jnp.argmax)
        }
        if (act) {
            bp[warp][t * K_ + lane] = (unsigned char)arg;
            score = m + em_t;
        }
    }
    if (act) score += end_t[lane];

    int best = 0; float bm = -3.0e38f;
#pragma unroll
    for (int jj = 0; jj < K_; jj++) {
        float sj = __shfl_sync(0xffffffffu, score, jj);
        if (sj > bm) { bm = sj; best = jj; }
    }
    __syncwarp();   // bp[] from lanes 1..8 visible to lane 0
    if (lane == 0) {
        int tag = best;
        out[b * T_ + (T_ - 1)] = (float)tag;
        for (int t = T_ - 2; t >= 0; t--) {
            tag = bp[warp][(t + 1) * K_ + tag];
            out[b * T_ + t] = (float)tag;
        }
    }
}

// ---------------- launch -------------------------------------------------------
extern "C" void kernel_launch(void* const* d_in, const int* in_sizes, int n_in,
                              void* d_out, int out_size)
{
    const int*   x      = (const int*)  d_in[0];
    const float* emb    = (const float*)d_in[1];
    const float* w_ih_f = (const float*)d_in[2];
    const float* w_hh_f = (const float*)d_in[3];
    const float* b_ih_f = (const float*)d_in[4];
    const float* b_hh_f = (const float*)d_in[5];
    const float* w_ih_b = (const float*)d_in[6];
    const float* w_hh_b = (const float*)d_in[7];
    const float* b_ih_b = (const float*)d_in[8];
    const float* b_hh_b = (const float*)d_in[9];
    const float* W_tag  = (const float*)d_in[10];
    const float* b_tag  = (const float*)d_in[11];
    const float* start_t= (const float*)d_in[12];
    const float* end_t  = (const float*)d_in[13];
    const float* trans  = (const float*)d_in[14];
    float* out = (float*)d_out;

    wtrans_kernel<<<128, 256>>>(w_hh_f, w_hh_b);
    proj_kernel<<<dim3(16, 1024), 256>>>(x, emb, w_ih_f, w_ih_b,
                                         b_ih_f, b_hh_f, b_ih_b, b_hh_b);
    lstm_kernel<<<64, 512>>>();
    emis_kernel<<<8192, 256>>>(W_tag, b_tag);
    viterbi_kernel<<<32, 128>>>(start_t, end_t, trans, out);
}

// round 10
// speedup vs baseline: 1.7630x; 1.4243x over previous
#include <cuda_runtime.h>
#include <math.h>
#include <stdint.h>

#define T_   512
#define B_   128
#define E_   128
#define HD_  128
#define G4_  512   // 4*HD
#define K_   9
#define V_   50000

typedef unsigned long long ull;

// ---------------- f32x2 packed-math helpers (FFMA2 — PTX-only on sm_103a) -----
__device__ __forceinline__ void fma2(ull& d, ull a, ull b) {
    asm("fma.rn.f32x2 %0, %1, %2, %0;" : "+l"(d) : "l"(a), "l"(b));
}
__device__ __forceinline__ ull dup2(float x) {
    ull r;
    asm("mov.b64 %0, {%1, %1};" : "=l"(r) : "f"(x));
    return r;
}
__device__ __forceinline__ float2 unpack2(ull v) {
    float2 f;
    asm("mov.b64 {%0, %1}, %2;" : "=f"(f.x), "=f"(f.y) : "l"(v));
    return f;
}

// ---------------- scratch (device globals; no runtime allocation) -------------
__device__ float g_Xf[(size_t)T_ * B_ * G4_];   // [t][b][512] fwd input proj + bias
__device__ float g_Xb[(size_t)T_ * B_ * G4_];   // backward
__device__ float g_H [(size_t)T_ * B_ * 256];   // [t][b][256] concat hidden
__device__ float g_emis[(size_t)B_ * T_ * K_];  // [b][t][k]

// ---------------- kernel A: embed gather + input projection GEMM --------------
// C[65536,1024] = gather(emb,x) @ [w_ih_f.T | w_ih_b.T] + (b_ih+b_hh)
// 64x64 tiles, k-major smem, f32x2 packed accumulation. grid (16,1024), blk 256.
__global__ void proj_kernel(const int* __restrict__ x, const float* __restrict__ emb,
                            const float* __restrict__ w_f, const float* __restrict__ w_b,
                            const float* __restrict__ bihf, const float* __restrict__ bhhf,
                            const float* __restrict__ bihb, const float* __restrict__ bhhb)
{
    __shared__ float As[64][72];      // [k][row], 72-pad keeps 16B row alignment
    __shared__ float Bs[64][72];      // [k][col]
    __shared__ float bias_s[64];
    __shared__ int   tok_s[64];

    const int tid = threadIdx.x;
    const int m0 = blockIdx.y * 64;
    const int n0 = blockIdx.x * 64;           // 0..1023
    const int dir = n0 >> 9;
    const int gbase = n0 & 511;
    const float* w  = dir ? w_b  : w_f;
    const float* bi = dir ? bihb : bihf;
    const float* bh = dir ? bhhb : bhhf;

    if (tid < 64) {
        int m = m0 + tid;
        int t = m >> 7, b = m & 127;
        int tok = x[b * T_ + t];
        if ((unsigned)tok >= (unsigned)V_) tok = 0;   // safety clamp
        tok_s[tid] = tok;
        int grow = gbase + tid;
        bias_s[tid] = bi[grow] + bh[grow];
    }
    __syncthreads();

    const int tx = tid & 15, ty = tid >> 4;   // micro tile: rows ty*4.., cols tx*4..
    ull acc[4][2];
#pragma unroll
    for (int i = 0; i < 4; i++) { acc[i][0] = 0ull; acc[i][1] = 0ull; }

    for (int kc = 0; kc < 128; kc += 64) {
        // fill transposed (k-major); coalesced global reads
        for (int idx = tid; idx < 4096; idx += 256) {
            int row = idx >> 6, kk = idx & 63;
            As[kk][row] = emb[(size_t)tok_s[row] * E_ + kc + kk];
            Bs[kk][row] = w[(size_t)(gbase + row) * E_ + kc + kk];
        }
        __syncthreads();

#pragma unroll 8
        for (int k = 0; k < 64; k++) {
            float4     av = *(const float4*)&As[k][ty * 4];
            ulonglong2 bv = *(const ulonglong2*)&Bs[k][tx * 4];  // 2 packed col-pairs
            ull a0 = dup2(av.x), a1 = dup2(av.y), a2 = dup2(av.z), a3 = dup2(av.w);
            fma2(acc[0][0], a0, bv.x); fma2(acc[0][1], a0, bv.y);
            fma2(acc[1][0], a1, bv.x); fma2(acc[1][1], a1, bv.y);
            fma2(acc[2][0], a2, bv.x); fma2(acc[2][1], a2, bv.y);
            fma2(acc[3][0], a3, bv.x); fma2(acc[3][1], a3, bv.y);
        }
        __syncthreads();
    }

    float* X = dir ? g_Xb : g_Xf;
    const int col = tx * 4;
#pragma unroll
    for (int i = 0; i < 4; i++) {
        int m = m0 + ty * 4 + i;
        float2 c01 = unpack2(acc[i][0]);
        float2 c23 = unpack2(acc[i][1]);
        float4 o = make_float4(c01.x + bias_s[col + 0], c01.y + bias_s[col + 1],
                               c23.x + bias_s[col + 2], c23.y + bias_s[col + 3]);
        *(float4*)&X[(size_t)m * G4_ + gbase + col] = o;
    }
}

// ---------------- kernel B: cluster-of-4 LSTM, W in registers -----------------
// 128 CTAs = 32 clusters of 4: cluster = (dir, batch-group of 8); rank = unit
// slice of 32. Each thread owns one gate row (W row in 128 registers) x 4
// batches. h exchanged via DSMEM double buffer + barrier.cluster each step.
// Per-batch gate accumulation order (k ascending) identical to prior rounds.
__global__ void __cluster_dims__(4, 1, 1) lstm_kernel(const float* __restrict__ whhf,
                                                      const float* __restrict__ whhb)
{
    __shared__ __align__(16) float hkb[2][HD_ * 8];   // [parity][k][b] 8KB
    __shared__ float gates_s[8][128];                 // [b][local row] 4KB

    const int tid = threadIdx.x;                      // 256 threads
    uint32_t rank;
    asm("mov.u32 %0, %%cluster_ctarank;" : "=r"(rank));
    const int cid = blockIdx.x >> 2;                  // 0..31
    const int dir = cid >> 4;
    const int b0  = (cid & 15) * 8;

    const float* Xin = dir ? g_Xb : g_Xf;
    const float* whh = dir ? whhb : whhf;

    // GEMM role: local row r (0..127), batch quad q (0..1)
    const int r = tid & 127;
    const int q = tid >> 7;
    const int grow = (r >> 5) * 128 + (int)rank * 32 + (r & 31);  // global gate row

    // W row -> registers (128 floats; fully-unrolled loop keeps them in regs)
    float wreg[128];
#pragma unroll
    for (int k = 0; k < 128; k += 4) {
        float4 v = *(const float4*)&whh[(size_t)grow * HD_ + k];
        wreg[k] = v.x; wreg[k + 1] = v.y; wreg[k + 2] = v.z; wreg[k + 3] = v.w;
    }

    // ACT role: unit-in-slice uu (0..31) = lane, batch bact (0..7) = warp
    const int uu = tid & 31, bact = tid >> 5;
    const int ug = (int)rank * 32 + uu;               // global unit 0..127

    // precompute DSMEM target addresses (per parity, per cluster CTA)
    uint32_t dstA[4], dstB[4];
    {
        uint32_t offA = (uint32_t)__cvta_generic_to_shared(&hkb[0][ug * 8 + bact]);
        uint32_t offB = (uint32_t)__cvta_generic_to_shared(&hkb[1][ug * 8 + bact]);
#pragma unroll
        for (int ctac = 0; ctac < 4; ctac++) {
            asm("mapa.shared::cluster.u32 %0, %1, %2;" : "=r"(dstA[ctac]) : "r"(offA), "r"(ctac));
            asm("mapa.shared::cluster.u32 %0, %1, %2;" : "=r"(dstB[ctac]) : "r"(offB), "r"(ctac));
        }
    }

    // zero initial h buffer 0
    for (int i = tid; i < HD_ * 8; i += 256) hkb[0][i] = 0.f;
    float c = 0.f;
    __syncthreads();
    asm volatile("barrier.cluster.arrive.aligned;" ::: "memory");
    asm volatile("barrier.cluster.wait.aligned;"   ::: "memory");

    for (int s = 0; s < T_; s++) {
        const int t = dir ? (T_ - 1 - s) : s;
        const float* hk = hkb[s & 1];

        // X prefetch (held through GEMM)
        const float* Xr = &Xin[(size_t)t * B_ * G4_ + (size_t)(b0 + bact) * G4_];
        float x0 = Xr[ug], x1 = Xr[128 + ug], x2 = Xr[256 + ug], x3 = Xr[384 + ug];

        // gates[b][r] = sum_k h[b][k] * W[r][k]   (h broadcast LDS, W in regs)
        ull a01 = 0ull, a23 = 0ull;
#pragma unroll
        for (int k = 0; k < 128; k++) {
            ulonglong2 hp = *(const ulonglong2*)&hk[k * 8 + q * 4];
            ull wd = dup2(wreg[k]);
            fma2(a01, wd, hp.x);
            fma2(a23, wd, hp.y);
        }
        {
            float2 g01 = unpack2(a01), g23 = unpack2(a23);
            gates_s[q * 4 + 0][r] = g01.x;
            gates_s[q * 4 + 1][r] = g01.y;
            gates_s[q * 4 + 2][r] = g23.x;
            gates_s[q * 4 + 3][r] = g23.y;
        }
        __syncthreads();

        // activation: thread owns (batch bact, unit ug)
        float pi = gates_s[bact][uu]      + x0;
        float pf = gates_s[bact][32 + uu] + x1;
        float pg = gates_s[bact][64 + uu] + x2;
        float po = gates_s[bact][96 + uu] + x3;
        float ig = 1.f / (1.f + expf(-pi));
        float fg = 1.f / (1.f + expf(-pf));
        float gg = tanhf(pg);
        float og = 1.f / (1.f + expf(-po));
        c = fg * c + ig * gg;
        float h = og * tanhf(c);

        // broadcast h into NEXT buffer of all 4 cluster CTAs (incl. self)
        const int np = (s + 1) & 1;
#pragma unroll
        for (int ctac = 0; ctac < 4; ctac++) {
            uint32_t d = np ? dstB[ctac] : dstA[ctac];
            asm volatile("st.shared::cluster.f32 [%0], %1;" :: "r"(d), "f"(h) : "memory");
        }
        g_H[(size_t)t * B_ * 256 + (size_t)(b0 + bact) * 256 + dir * 128 + ug] = h;

        // cluster barrier: release/acquire orders DSMEM stores; also protects
        // gates_s reuse next step (full CTA barrier semantics).
        asm volatile("barrier.cluster.arrive.aligned;" ::: "memory");
        asm volatile("barrier.cluster.wait.aligned;"   ::: "memory");
    }
}

// ---------------- kernel C: emissions = H @ W_tag.T + b_tag -------------------
__global__ void emis_kernel(const float* __restrict__ W_tag, const float* __restrict__ b_tag)
{
    __shared__ float Ws[K_ * 256];
    __shared__ float bs[K_];
    const int tid = threadIdx.x;
    for (int i = tid; i < K_ * 256; i += 256) Ws[i] = W_tag[i];
    if (tid < K_) bs[tid] = b_tag[tid];
    __syncthreads();

    const int warp = tid >> 5, lane = tid & 31;
    const int rr = blockIdx.x * 8 + warp;          // row in [t*128+b]
    const float* hrow = &g_H[(size_t)rr * 256];
    float hv[8];
#pragma unroll
    for (int i = 0; i < 8; i++) hv[i] = hrow[lane + 32 * i];
    const int t = rr >> 7, b = rr & 127;
#pragma unroll
    for (int k = 0; k < K_; k++) {
        float s = 0.f;
#pragma unroll
        for (int i = 0; i < 8; i++) s += hv[i] * Ws[k * 256 + lane + 32 * i];
#pragma unroll
        for (int off = 16; off > 0; off >>= 1) s += __shfl_down_sync(0xffffffffu, s, off);
        if (lane == 0) g_emis[(size_t)b * T_ * K_ + t * K_ + k] = s + bs[k];
    }
}

// ---------------- kernel D: CRF Viterbi — one warp per batch ------------------
// Output written as FLOAT32 (harness compares output buffer as f32).
__global__ void viterbi_kernel(const float* __restrict__ start_t, const float* __restrict__ end_t,
                               const float* __restrict__ trans, float* __restrict__ out)
{
    __shared__ unsigned char bp[4][T_ * K_];   // 18432 bytes
    const int tid = threadIdx.x, warp = tid >> 5, lane = tid & 31;
    const int b = blockIdx.x * 4 + warp;

    const float* emp = &g_emis[(size_t)b * T_ * K_];
    const bool act = (lane < K_);

    float tr[K_];
    float score;
    if (act) {
#pragma unroll
        for (int i = 0; i < K_; i++) tr[i] = trans[i * K_ + lane];
        score = start_t[lane] + __ldg(&emp[lane]);
    } else {
#pragma unroll
        for (int i = 0; i < K_; i++) tr[i] = 0.f;
        score = -3.0e38f;
    }
    __syncwarp();

    for (int t = 1; t < T_; t++) {
        float em_t = act ? __ldg(&emp[t * K_ + lane]) : 0.f;
        float m = -3.0e38f; int arg = 0;
#pragma unroll
        for (int i = 0; i < K_; i++) {
            float si = __shfl_sync(0xffffffffu, score, i);
            float v = si + tr[i];
            if (v > m) { m = v; arg = i; }   // strict > keeps first max (jnp.argmax)
        }
        if (act) {
            bp[warp][t * K_ + lane] = (unsigned char)arg;
            score = m + em_t;
        }
    }
    if (act) score += end_t[lane];

    int best = 0; float bm = -3.0e38f;
#pragma unroll
    for (int jj = 0; jj < K_; jj++) {
        float sj = __shfl_sync(0xffffffffu, score, jj);
        if (sj > bm) { bm = sj; best = jj; }
    }
    __syncwarp();   // bp[] from lanes 1..8 visible to lane 0
    if (lane == 0) {
        int tag = best;
        out[b * T_ + (T_ - 1)] = (float)tag;
        for (int t = T_ - 2; t >= 0; t--) {
            tag = bp[warp][(t + 1) * K_ + tag];
            out[b * T_ + t] = (float)tag;
        }
    }
}

// ---------------- launch -------------------------------------------------------
extern "C" void kernel_launch(void* const* d_in, const int* in_sizes, int n_in,
                              void* d_out, int out_size)
{
    const int*   x      = (const int*)  d_in[0];
    const float* emb    = (const float*)d_in[1];
    const float* w_ih_f = (const float*)d_in[2];
    const float* w_hh_f = (const float*)d_in[3];
    const float* b_ih_f = (const float*)d_in[4];
    const float* b_hh_f = (const float*)d_in[5];
    const float* w_ih_b = (const float*)d_in[6];
    const float* w_hh_b = (const float*)d_in[7];
    const float* b_ih_b = (const float*)d_in[8];
    const float* b_hh_b = (const float*)d_in[9];
    const float* W_tag  = (const float*)d_in[10];
    const float* b_tag  = (const float*)d_in[11];
    const float* start_t= (const float*)d_in[12];
    const float* end_t  = (const float*)d_in[13];
    const float* trans  = (const float*)d_in[14];
    float* out = (float*)d_out;

    proj_kernel<<<dim3(16, 1024), 256>>>(x, emb, w_ih_f, w_ih_b,
                                         b_ih_f, b_hh_f, b_ih_b, b_hh_b);
    lstm_kernel<<<128, 256>>>(w_hh_f, w_hh_b);
    emis_kernel<<<8192, 256>>>(W_tag, b_tag);
    viterbi_kernel<<<32, 128>>>(start_t, end_t, trans, out);
}

// round 11
// speedup vs baseline: 1.7806x; 1.0100x over previous
#include <cuda_runtime.h>
#include <math.h>
#include <stdint.h>

#define T_   512
#define B_   128
#define E_   128
#define HD_  128
#define G4_  512   // 4*HD
#define K_   9
#define V_   50000

typedef unsigned long long ull;

// ---------------- f32x2 packed-math helpers (FFMA2 — PTX-only on sm_103a) -----
__device__ __forceinline__ void fma2(ull& d, ull a, ull b) {
    asm("fma.rn.f32x2 %0, %1, %2, %0;" : "+l"(d) : "l"(a), "l"(b));
}
__device__ __forceinline__ ull dup2(float x) {
    ull r;
    asm("mov.b64 %0, {%1, %1};" : "=l"(r) : "f"(x));
    return r;
}
__device__ __forceinline__ float2 unpack2(ull v) {
    float2 f;
    asm("mov.b64 {%0, %1}, %2;" : "=f"(f.x), "=f"(f.y) : "l"(v));
    return f;
}

// ---------------- scratch (device globals; no runtime allocation) -------------
__device__ float g_Xf[(size_t)T_ * B_ * G4_];   // [t][b][512] fwd input proj + bias
__device__ float g_Xb[(size_t)T_ * B_ * G4_];   // backward
__device__ float g_H [(size_t)T_ * B_ * 256];   // [t][b][256] concat hidden
__device__ float g_emis[(size_t)B_ * T_ * K_];  // [b][t][k]

// ---------------- kernel A: embed gather + input projection GEMM --------------
// C[65536,1024] = gather(emb,x) @ [w_ih_f.T | w_ih_b.T] + (b_ih+b_hh)
// 64x64 tiles, k-major smem, f32x2 packed accumulation. grid (16,1024), blk 256.
__global__ void __launch_bounds__(256) proj_kernel(
                            const int* __restrict__ x, const float* __restrict__ emb,
                            const float* __restrict__ w_f, const float* __restrict__ w_b,
                            const float* __restrict__ bihf, const float* __restrict__ bhhf,
                            const float* __restrict__ bihb, const float* __restrict__ bhhb)
{
    __shared__ float As[64][72];      // [k][row], 72-pad keeps 16B row alignment
    __shared__ float Bs[64][72];      // [k][col]
    __shared__ float bias_s[64];
    __shared__ int   tok_s[64];

    const int tid = threadIdx.x;
    const int m0 = blockIdx.y * 64;
    const int n0 = blockIdx.x * 64;           // 0..1023
    const int dir = n0 >> 9;
    const int gbase = n0 & 511;
    const float* w  = dir ? w_b  : w_f;
    const float* bi = dir ? bihb : bihf;
    const float* bh = dir ? bhhb : bhhf;

    if (tid < 64) {
        int m = m0 + tid;
        int t = m >> 7, b = m & 127;
        int tok = x[b * T_ + t];
        if ((unsigned)tok >= (unsigned)V_) tok = 0;   // safety clamp
        tok_s[tid] = tok;
        int grow = gbase + tid;
        bias_s[tid] = bi[grow] + bh[grow];
    }
    __syncthreads();

    const int tx = tid & 15, ty = tid >> 4;   // micro tile: rows ty*4.., cols tx*4..
    ull acc[4][2];
#pragma unroll
    for (int i = 0; i < 4; i++) { acc[i][0] = 0ull; acc[i][1] = 0ull; }

    for (int kc = 0; kc < 128; kc += 64) {
        // fill transposed (k-major); coalesced global reads
        for (int idx = tid; idx < 4096; idx += 256) {
            int row = idx >> 6, kk = idx & 63;
            As[kk][row] = emb[(size_t)tok_s[row] * E_ + kc + kk];
            Bs[kk][row] = w[(size_t)(gbase + row) * E_ + kc + kk];
        }
        __syncthreads();

#pragma unroll 8
        for (int k = 0; k < 64; k++) {
            float4     av = *(const float4*)&As[k][ty * 4];
            ulonglong2 bv = *(const ulonglong2*)&Bs[k][tx * 4];  // 2 packed col-pairs
            ull a0 = dup2(av.x), a1 = dup2(av.y), a2 = dup2(av.z), a3 = dup2(av.w);
            fma2(acc[0][0], a0, bv.x); fma2(acc[0][1], a0, bv.y);
            fma2(acc[1][0], a1, bv.x); fma2(acc[1][1], a1, bv.y);
            fma2(acc[2][0], a2, bv.x); fma2(acc[2][1], a2, bv.y);
            fma2(acc[3][0], a3, bv.x); fma2(acc[3][1], a3, bv.y);
        }
        __syncthreads();
    }

    float* X = dir ? g_Xb : g_Xf;
    const int col = tx * 4;
#pragma unroll
    for (int i = 0; i < 4; i++) {
        int m = m0 + ty * 4 + i;
        float2 c01 = unpack2(acc[i][0]);
        float2 c23 = unpack2(acc[i][1]);
        float4 o = make_float4(c01.x + bias_s[col + 0], c01.y + bias_s[col + 1],
                               c23.x + bias_s[col + 2], c23.y + bias_s[col + 3]);
        *(float4*)&X[(size_t)m * G4_ + gbase + col] = o;
    }
}

// ---------------- kernel B: cluster-of-4 LSTM, W in registers -----------------
// 128 CTAs = 32 clusters of 4: cluster = (dir, batch-group of 8); rank = unit
// slice of 32. Each thread owns one gate row (W row in 128 registers) x 4
// batches. h exchanged via DSMEM double buffer + barrier.cluster each step.
// __launch_bounds__(256,1): full register budget -> wreg[128] must NOT spill.
__global__ void __cluster_dims__(4, 1, 1) __launch_bounds__(256, 1)
lstm_kernel(const float* __restrict__ whhf, const float* __restrict__ whhb)
{
    __shared__ __align__(16) float hkb[2][HD_ * 8];   // [parity][k][b] 8KB
    __shared__ float gates_s[8][128];                 // [b][local row] 4KB

    const int tid = threadIdx.x;                      // 256 threads
    uint32_t rank;
    asm("mov.u32 %0, %%cluster_ctarank;" : "=r"(rank));
    const int cid = blockIdx.x >> 2;                  // 0..31
    const int dir = cid >> 4;
    const int b0  = (cid & 15) * 8;

    const float* Xin = dir ? g_Xb : g_Xf;
    const float* whh = dir ? whhb : whhf;

    // GEMM role: local row r (0..127), batch quad q (0..1)
    const int r = tid & 127;
    const int q = tid >> 7;
    const int grow = (r >> 5) * 128 + (int)rank * 32 + (r & 31);  // global gate row

    // W row -> registers (128 floats; fully-unrolled loop keeps them in regs)
    float wreg[128];
#pragma unroll
    for (int k = 0; k < 128; k += 4) {
        float4 v = *(const float4*)&whh[(size_t)grow * HD_ + k];
        wreg[k] = v.x; wreg[k + 1] = v.y; wreg[k + 2] = v.z; wreg[k + 3] = v.w;
    }

    // ACT role: unit-in-slice uu (0..31) = lane, batch bact (0..7) = warp
    const int uu = tid & 31, bact = tid >> 5;
    const int ug = (int)rank * 32 + uu;               // global unit 0..127

    // precompute DSMEM target addresses (per parity, per cluster CTA)
    uint32_t dstA[4], dstB[4];
    {
        uint32_t offA = (uint32_t)__cvta_generic_to_shared(&hkb[0][ug * 8 + bact]);
        uint32_t offB = (uint32_t)__cvta_generic_to_shared(&hkb[1][ug * 8 + bact]);
#pragma unroll
        for (int ctac = 0; ctac < 4; ctac++) {
            asm("mapa.shared::cluster.u32 %0, %1, %2;" : "=r"(dstA[ctac]) : "r"(offA), "r"(ctac));
            asm("mapa.shared::cluster.u32 %0, %1, %2;" : "=r"(dstB[ctac]) : "r"(offB), "r"(ctac));
        }
    }

    // zero initial h buffer 0
    for (int i = tid; i < HD_ * 8; i += 256) hkb[0][i] = 0.f;
    float c = 0.f;
    __syncthreads();
    asm volatile("barrier.cluster.arrive.aligned;" ::: "memory");
    asm volatile("barrier.cluster.wait.aligned;"   ::: "memory");

    for (int s = 0; s < T_; s++) {
        const int t = dir ? (T_ - 1 - s) : s;
        const float* hk = hkb[s & 1];

        // X prefetch (held through GEMM)
        const float* Xr = &Xin[(size_t)t * B_ * G4_ + (size_t)(b0 + bact) * G4_];
        float x0 = Xr[ug], x1 = Xr[128 + ug], x2 = Xr[256 + ug], x3 = Xr[384 + ug];

        // gates[b][r] = sum_k h[b][k] * W[r][k]   (h broadcast LDS, W in regs)
        ull a01 = 0ull, a23 = 0ull;
#pragma unroll
        for (int k = 0; k < 128; k++) {
            ulonglong2 hp = *(const ulonglong2*)&hk[k * 8 + q * 4];
            ull wd = dup2(wreg[k]);
            fma2(a01, wd, hp.x);
            fma2(a23, wd, hp.y);
        }
        {
            float2 g01 = unpack2(a01), g23 = unpack2(a23);
            gates_s[q * 4 + 0][r] = g01.x;
            gates_s[q * 4 + 1][r] = g01.y;
            gates_s[q * 4 + 2][r] = g23.x;
            gates_s[q * 4 + 3][r] = g23.y;
        }
        __syncthreads();

        // activation: thread owns (batch bact, unit ug)
        float pi = gates_s[bact][uu]      + x0;
        float pf = gates_s[bact][32 + uu] + x1;
        float pg = gates_s[bact][64 + uu] + x2;
        float po = gates_s[bact][96 + uu] + x3;
        float ig = 1.f / (1.f + expf(-pi));
        float fg = 1.f / (1.f + expf(-pf));
        float gg = tanhf(pg);
        float og = 1.f / (1.f + expf(-po));
        c = fg * c + ig * gg;
        float h = og * tanhf(c);

        // broadcast h into NEXT buffer of all 4 cluster CTAs (incl. self)
        const int np = (s + 1) & 1;
#pragma unroll
        for (int ctac = 0; ctac < 4; ctac++) {
            uint32_t d = np ? dstB[ctac] : dstA[ctac];
            asm volatile("st.shared::cluster.f32 [%0], %1;" :: "r"(d), "f"(h) : "memory");
        }
        g_H[(size_t)t * B_ * 256 + (size_t)(b0 + bact) * 256 + dir * 128 + ug] = h;

        // cluster barrier: release/acquire orders DSMEM stores; also protects
        // gates_s reuse next step (full CTA barrier semantics).
        asm volatile("barrier.cluster.arrive.aligned;" ::: "memory");
        asm volatile("barrier.cluster.wait.aligned;"   ::: "memory");
    }
}

// ---------------- kernel C: emissions = H @ W_tag.T + b_tag -------------------
__global__ void emis_kernel(const float* __restrict__ W_tag, const float* __restrict__ b_tag)
{
    __shared__ float Ws[K_ * 256];
    __shared__ float bs[K_];
    const int tid = threadIdx.x;
    for (int i = tid; i < K_ * 256; i += 256) Ws[i] = W_tag[i];
    if (tid < K_) bs[tid] = b_tag[tid];
    __syncthreads();

    const int warp = tid >> 5, lane = tid & 31;
    const int rr = blockIdx.x * 8 + warp;          // row in [t*128+b]
    const float* hrow = &g_H[(size_t)rr * 256];
    float hv[8];
#pragma unroll
    for (int i = 0; i < 8; i++) hv[i] = hrow[lane + 32 * i];
    const int t = rr >> 7, b = rr & 127;
#pragma unroll
    for (int k = 0; k < K_; k++) {
        float s = 0.f;
#pragma unroll
        for (int i = 0; i < 8; i++) s += hv[i] * Ws[k * 256 + lane + 32 * i];
#pragma unroll
        for (int off = 16; off > 0; off >>= 1) s += __shfl_down_sync(0xffffffffu, s, off);
        if (lane == 0) g_emis[(size_t)b * T_ * K_ + t * K_ + k] = s + bs[k];
    }
}

// ---------------- kernel D: CRF Viterbi — SMEM-staged emissions ---------------
// 64 CTAs x 2 warps, one batch per warp. Emissions bulk-staged to SMEM (float4)
// so the 511-step scan hits LDS (29 cyc) instead of dependent L2 loads.
// Output written as FLOAT32 (harness compares output buffer as f32).
__global__ void __launch_bounds__(64) viterbi_kernel(
                               const float* __restrict__ start_t, const float* __restrict__ end_t,
                               const float* __restrict__ trans, float* __restrict__ out)
{
    __shared__ float em_s[2][T_ * K_];          // 36864 B
    __shared__ unsigned char bp[2][T_ * K_];    //  9216 B
    const int tid = threadIdx.x, warp = tid >> 5, lane = tid & 31;
    const int b = blockIdx.x * 2 + warp;

    // bulk stage: 4608 floats = 1152 float4 per warp, coalesced
    {
        const float4* src = (const float4*)&g_emis[(size_t)b * T_ * K_];
        float4* dst = (float4*)em_s[warp];
        for (int i = lane; i < (T_ * K_) / 4; i += 32) dst[i] = src[i];
    }
    __syncwarp();

    const float* em = em_s[warp];
    const bool act = (lane < K_);

    float tr[K_];
    float score;
    if (act) {
#pragma unroll
        for (int i = 0; i < K_; i++) tr[i] = trans[i * K_ + lane];
        score = start_t[lane] + em[lane];
    } else {
#pragma unroll
        for (int i = 0; i < K_; i++) tr[i] = 0.f;
        score = -3.0e38f;
    }
    __syncwarp();

    for (int t = 1; t < T_; t++) {
        float em_t = act ? em[t * K_ + lane] : 0.f;
        float m = -3.0e38f; int arg = 0;
#pragma unroll
        for (int i = 0; i < K_; i++) {
            float si = __shfl_sync(0xffffffffu, score, i);
            float v = si + tr[i];
            if (v > m) { m = v; arg = i; }   // strict > keeps first max (jnp.argmax)
        }
        if (act) {
            bp[warp][t * K_ + lane] = (unsigned char)arg;
            score = m + em_t;
        }
    }
    if (act) score += end_t[lane];

    int best = 0; float bm = -3.0e38f;
#pragma unroll
    for (int jj = 0; jj < K_; jj++) {
        float sj = __shfl_sync(0xffffffffu, score, jj);
        if (sj > bm) { bm = sj; best = jj; }
    }
    __syncwarp();   // bp[] from lanes 1..8 visible to lane 0
    if (lane == 0) {
        int tag = best;
        out[b * T_ + (T_ - 1)] = (float)tag;
        for (int t = T_ - 2; t >= 0; t--) {
            tag = bp[warp][(t + 1) * K_ + tag];
            out[b * T_ + t] = (float)tag;
        }
    }
}

// ---------------- launch -------------------------------------------------------
extern "C" void kernel_launch(void* const* d_in, const int* in_sizes, int n_in,
                              void* d_out, int out_size)
{
    const int*   x      = (const int*)  d_in[0];
    const float* emb    = (const float*)d_in[1];
    const float* w_ih_f = (const float*)d_in[2];
    const float* w_hh_f = (const float*)d_in[3];
    const float* b_ih_f = (const float*)d_in[4];
    const float* b_hh_f = (const float*)d_in[5];
    const float* w_ih_b = (const float*)d_in[6];
    const float* w_hh_b = (const float*)d_in[7];
    const float* b_ih_b = (const float*)d_in[8];
    const float* b_hh_b = (const float*)d_in[9];
    const float* W_tag  = (const float*)d_in[10];
    const float* b_tag  = (const float*)d_in[11];
    const float* start_t= (const float*)d_in[12];
    const float* end_t  = (const float*)d_in[13];
    const float* trans  = (const float*)d_in[14];
    float* out = (float*)d_out;

    proj_kernel<<<dim3(16, 1024), 256>>>(x, emb, w_ih_f, w_ih_b,
                                         b_ih_f, b_hh_f, b_ih_b, b_hh_b);
    lstm_kernel<<<128, 256>>>(w_hh_f, w_hh_b);
    emis_kernel<<<8192, 256>>>(W_tag, b_tag);
    viterbi_kernel<<<64, 64>>>(start_t, end_t, trans, out);
}

// round 12
// speedup vs baseline: 1.8741x; 1.0525x over previous
#include <cuda_runtime.h>
#include <math.h>
#include <stdint.h>

#define T_   512
#define B_   128
#define E_   128
#define HD_  128
#define G4_  512   // 4*HD
#define K_   9
#define V_   50000

typedef unsigned long long ull;

// ---------------- f32x2 packed-math helpers (FFMA2 — PTX-only on sm_103a) -----
__device__ __forceinline__ void fma2(ull& d, ull a, ull b) {
    asm("fma.rn.f32x2 %0, %1, %2, %0;" : "+l"(d) : "l"(a), "l"(b));
}
__device__ __forceinline__ ull dup2(float x) {
    ull r;
    asm("mov.b64 %0, {%1, %1};" : "=l"(r) : "f"(x));
    return r;
}
__device__ __forceinline__ float2 unpack2(ull v) {
    float2 f;
    asm("mov.b64 {%0, %1}, %2;" : "=f"(f.x), "=f"(f.y) : "l"(v));
    return f;
}

// ---------------- scratch (device globals; no runtime allocation) -------------
__device__ float g_Xf[(size_t)T_ * B_ * G4_];   // [t][b][512] fwd input proj + bias
__device__ float g_Xb[(size_t)T_ * B_ * G4_];   // backward
__device__ float g_H [(size_t)T_ * B_ * 256];   // [t][b][256] concat hidden
__device__ float g_emis[(size_t)B_ * T_ * K_];  // [b][t][k]

// ---------------- kernel A: embed gather + input projection GEMM --------------
__global__ void __launch_bounds__(256) proj_kernel(
                            const int* __restrict__ x, const float* __restrict__ emb,
                            const float* __restrict__ w_f, const float* __restrict__ w_b,
                            const float* __restrict__ bihf, const float* __restrict__ bhhf,
                            const float* __restrict__ bihb, const float* __restrict__ bhhb)
{
    __shared__ float As[64][72];      // [k][row], 72-pad keeps 16B row alignment
    __shared__ float Bs[64][72];      // [k][col]
    __shared__ float bias_s[64];
    __shared__ int   tok_s[64];

    const int tid = threadIdx.x;
    const int m0 = blockIdx.y * 64;
    const int n0 = blockIdx.x * 64;           // 0..1023
    const int dir = n0 >> 9;
    const int gbase = n0 & 511;
    const float* w  = dir ? w_b  : w_f;
    const float* bi = dir ? bihb : bihf;
    const float* bh = dir ? bhhb : bhhf;

    if (tid < 64) {
        int m = m0 + tid;
        int t = m >> 7, b = m & 127;
        int tok = x[b * T_ + t];
        if ((unsigned)tok >= (unsigned)V_) tok = 0;   // safety clamp
        tok_s[tid] = tok;
        int grow = gbase + tid;
        bias_s[tid] = bi[grow] + bh[grow];
    }
    __syncthreads();

    const int tx = tid & 15, ty = tid >> 4;
    ull acc[4][2];
#pragma unroll
    for (int i = 0; i < 4; i++) { acc[i][0] = 0ull; acc[i][1] = 0ull; }

    for (int kc = 0; kc < 128; kc += 64) {
        for (int idx = tid; idx < 4096; idx += 256) {
            int row = idx >> 6, kk = idx & 63;
            As[kk][row] = emb[(size_t)tok_s[row] * E_ + kc + kk];
            Bs[kk][row] = w[(size_t)(gbase + row) * E_ + kc + kk];
        }
        __syncthreads();

#pragma unroll 8
        for (int k = 0; k < 64; k++) {
            float4     av = *(const float4*)&As[k][ty * 4];
            ulonglong2 bv = *(const ulonglong2*)&Bs[k][tx * 4];
            ull a0 = dup2(av.x), a1 = dup2(av.y), a2 = dup2(av.z), a3 = dup2(av.w);
            fma2(acc[0][0], a0, bv.x); fma2(acc[0][1], a0, bv.y);
            fma2(acc[1][0], a1, bv.x); fma2(acc[1][1], a1, bv.y);
            fma2(acc[2][0], a2, bv.x); fma2(acc[2][1], a2, bv.y);
            fma2(acc[3][0], a3, bv.x); fma2(acc[3][1], a3, bv.y);
        }
        __syncthreads();
    }

    float* X = dir ? g_Xb : g_Xf;
    const int col = tx * 4;
#pragma unroll
    for (int i = 0; i < 4; i++) {
        int m = m0 + ty * 4 + i;
        float2 c01 = unpack2(acc[i][0]);
        float2 c23 = unpack2(acc[i][1]);
        float4 o = make_float4(c01.x + bias_s[col + 0], c01.y + bias_s[col + 1],
                               c23.x + bias_s[col + 2], c23.y + bias_s[col + 3]);
        *(float4*)&X[(size_t)m * G4_ + gbase + col] = o;
    }
}

// ---------------- kernel B: cluster-of-4 LSTM, k-split, mbarrier handoff ------
// 128 CTAs = 32 clusters of 4. CTA: 512 threads, 128 gate rows; each thread
// owns HALF a W row (64 regs) x 4 batches -> 4 warps/SMSP for latency hiding.
// h exchanged via DSMEM; sync via per-CTA mbarrier pair (acquire/release,
// ~90 cyc wakeup) instead of barrier.cluster (~490 cyc).
__global__ void __cluster_dims__(4, 1, 1) __launch_bounds__(512, 1)
lstm_kernel(const float* __restrict__ whhf, const float* __restrict__ whhb)
{
    __shared__ __align__(16) float hkb[2][HD_ * 8];   // [parity][k][b] 8KB
    __shared__ float g0[8][128];                      // k-half 0 partials
    __shared__ float g1[8][128];                      // k-half 1 partials
    __shared__ __align__(8) unsigned long long mbar[2];

    const int tid = threadIdx.x;                      // 512 threads
    uint32_t rank;
    asm("mov.u32 %0, %%cluster_ctarank;" : "=r"(rank));
    const int cid = blockIdx.x >> 2;                  // 0..31
    const int dir = cid >> 4;
    const int b0  = (cid & 15) * 8;

    const float* Xin = dir ? g_Xb : g_Xf;
    const float* whh = dir ? whhb : whhf;

    // GEMM role: local row r, batch quad q, k-half
    const int r    = tid & 127;
    const int q    = (tid >> 7) & 1;
    const int half = tid >> 8;
    const int grow = (r >> 5) * 128 + (int)rank * 32 + (r & 31);

    float wreg[64];
#pragma unroll
    for (int k = 0; k < 64; k += 4) {
        float4 v = *(const float4*)&whh[(size_t)grow * HD_ + half * 64 + k];
        wreg[k] = v.x; wreg[k + 1] = v.y; wreg[k + 2] = v.z; wreg[k + 3] = v.w;
    }

    // ACT role (threads 0..255): unit uu, batch bact
    const int uu = tid & 31, bact = (tid >> 5) & 7;
    const int ug = (int)rank * 32 + uu;
    const bool is_act = (tid < 256);

    if (tid == 0) {
        uint32_t mb = (uint32_t)__cvta_generic_to_shared(&mbar[0]);
        asm volatile("mbarrier.init.shared.b64 [%0], 4;" :: "r"(mb) : "memory");
        asm volatile("mbarrier.init.shared.b64 [%0], 4;" :: "r"(mb + 8) : "memory");
    }
    for (int i = tid; i < HD_ * 8; i += 512) hkb[0][i] = 0.f;
    float c = 0.f;
    int ph0 = 0, ph1 = 0;
    __syncthreads();
    // cluster rally: all mbarriers initialized before any remote arrive
    asm volatile("barrier.cluster.arrive.aligned;" ::: "memory");
    asm volatile("barrier.cluster.wait.aligned;"   ::: "memory");

    const uint32_t mb_base = (uint32_t)__cvta_generic_to_shared(&mbar[0]);
    const uint32_t h_off0  = is_act
        ? (uint32_t)__cvta_generic_to_shared(&hkb[0][ug * 8 + bact]) : 0u;

    for (int s = 0; s < T_; s++) {
        const int t = dir ? (T_ - 1 - s) : s;

        // X prefetch BEFORE the wait (global, h-independent -> overlaps sync)
        float x0 = 0.f, x1 = 0.f, x2 = 0.f, x3 = 0.f;
        if (is_act) {
            const float* Xr = &Xin[(size_t)t * B_ * G4_ + (size_t)(b0 + bact) * G4_];
            x0 = Xr[ug]; x1 = Xr[128 + ug]; x2 = Xr[256 + ug]; x3 = Xr[384 + ug];
        }

        // wait until h buffer (s&1) is full in MY smem (acquire, cluster scope)
        if (s > 0) {
            const uint32_t mb = mb_base + (uint32_t)(s & 1) * 8u;
            const int par = (s & 1) ? ph1 : ph0;
            uint32_t done;
            asm volatile(
                "{\n\t.reg .pred p;\n\t"
                "mbarrier.try_wait.parity.acquire.cluster.shared::cta.b64 p, [%1], %2;\n\t"
                "selp.b32 %0, 1, 0, p;\n\t}"
                : "=r"(done) : "r"(mb), "r"(par) : "memory");
            if (!done) {
                asm volatile(
                    "{\n\t.reg .pred P1;\n\t"
                    "WL_%=:\n\t"
                    "mbarrier.try_wait.parity.acquire.cluster.shared::cta.b64 P1, [%0], %1, 0x989680;\n\t"
                    "@P1 bra.uni WD_%=;\n\t"
                    "bra.uni WL_%=;\n\t"
                    "WD_%=:\n\t}"
                    :: "r"(mb), "r"(par) : "memory");
            }
            if (s & 1) ph1 ^= 1; else ph0 ^= 1;
        }

        // GEMM partial: sum over my k-half (h broadcast LDS, W in regs)
        const float* hk = hkb[s & 1] + half * 64 * 8;
        ull a01 = 0ull, a23 = 0ull;
#pragma unroll
        for (int k = 0; k < 64; k++) {
            ulonglong2 hp = *(const ulonglong2*)&hk[k * 8 + q * 4];
            ull wd = dup2(wreg[k]);
            fma2(a01, wd, hp.x);
            fma2(a23, wd, hp.y);
        }
        {
            float2 p01 = unpack2(a01), p23 = unpack2(a23);
            float (*gs)[128] = half ? g1 : g0;
            gs[q * 4 + 0][r] = p01.x;
            gs[q * 4 + 1][r] = p01.y;
            gs[q * 4 + 2][r] = p23.x;
            gs[q * 4 + 3][r] = p23.y;
        }
        __syncthreads();

        // activation + h broadcast
        if (is_act) {
            float pi = g0[bact][uu]      + g1[bact][uu]      + x0;
            float pf = g0[bact][32 + uu] + g1[bact][32 + uu] + x1;
            float pg = g0[bact][64 + uu] + g1[bact][64 + uu] + x2;
            float po = g0[bact][96 + uu] + g1[bact][96 + uu] + x3;
            float ig = 1.f / (1.f + expf(-pi));
            float fg = 1.f / (1.f + expf(-pf));
            float gg = tanhf(pg);
            float og = 1.f / (1.f + expf(-po));
            c = fg * c + ig * gg;
            float h = og * tanhf(c);

            if (s < T_ - 1) {
                const uint32_t off = h_off0 + (uint32_t)((s + 1) & 1) * (HD_ * 8 * 4);
#pragma unroll
                for (int ctac = 0; ctac < 4; ctac++) {
                    uint32_t rem;
                    asm("mapa.shared::cluster.u32 %0, %1, %2;" : "=r"(rem) : "r"(off), "r"(ctac));
                    asm volatile("st.shared::cluster.f32 [%0], %1;" :: "r"(rem), "f"(h) : "memory");
                }
            }
            g_H[(size_t)t * B_ * 256 + (size_t)(b0 + bact) * 256 + dir * 128 + ug] = h;
        }
        __syncthreads();   // all stores issued CTA-wide; also protects g0/g1 reuse

        // publish: one arrive per destination CTA (count=4 at each barrier)
        if (s < T_ - 1 && tid < 4) {
            asm volatile("fence.acq_rel.cluster;" ::: "memory");
            const uint32_t loc = mb_base + (uint32_t)((s + 1) & 1) * 8u;
            uint32_t rem;
            asm("mapa.shared::cluster.u32 %0, %1, %2;" : "=r"(rem) : "r"(loc), "r"(tid));
            asm volatile("mbarrier.arrive.release.cluster.shared::cluster.b64 _, [%0];"
                         :: "r"(rem) : "memory");
        }
    }

    // final rally: no CTA exits while peers might still touch its SMEM
    asm volatile("barrier.cluster.arrive.aligned;" ::: "memory");
    asm volatile("barrier.cluster.wait.aligned;"   ::: "memory");
}

// ---------------- kernel C: emissions = H @ W_tag.T + b_tag -------------------
__global__ void emis_kernel(const float* __restrict__ W_tag, const float* __restrict__ b_tag)
{
    __shared__ float Ws[K_ * 256];
    __shared__ float bs[K_];
    const int tid = threadIdx.x;
    for (int i = tid; i < K_ * 256; i += 256) Ws[i] = W_tag[i];
    if (tid < K_) bs[tid] = b_tag[tid];
    __syncthreads();

    const int warp = tid >> 5, lane = tid & 31;
    const int rr = blockIdx.x * 8 + warp;          // row in [t*128+b]
    const float* hrow = &g_H[(size_t)rr * 256];
    float hv[8];
#pragma unroll
    for (int i = 0; i < 8; i++) hv[i] = hrow[lane + 32 * i];
    const int t = rr >> 7, b = rr & 127;
#pragma unroll
    for (int k = 0; k < K_; k++) {
        float s = 0.f;
#pragma unroll
        for (int i = 0; i < 8; i++) s += hv[i] * Ws[k * 256 + lane + 32 * i];
#pragma unroll
        for (int off = 16; off > 0; off >>= 1) s += __shfl_down_sync(0xffffffffu, s, off);
        if (lane == 0) g_emis[(size_t)b * T_ * K_ + t * K_ + k] = s + bs[k];
    }
}

// ---------------- kernel D: CRF Viterbi — SMEM-staged emissions ---------------
__global__ void __launch_bounds__(64) viterbi_kernel(
                               const float* __restrict__ start_t, const float* __restrict__ end_t,
                               const float* __restrict__ trans, float* __restrict__ out)
{
    __shared__ float em_s[2][T_ * K_];          // 36864 B
    __shared__ unsigned char bp[2][T_ * K_];    //  9216 B
    const int tid = threadIdx.x, warp = tid >> 5, lane = tid & 31;
    const int b = blockIdx.x * 2 + warp;

    {
        const float4* src = (const float4*)&g_emis[(size_t)b * T_ * K_];
        float4* dst = (float4*)em_s[warp];
        for (int i = lane; i < (T_ * K_) / 4; i += 32) dst[i] = src[i];
    }
    __syncwarp();

    const float* em = em_s[warp];
    const bool act = (lane < K_);

    float tr[K_];
    float score;
    if (act) {
#pragma unroll
        for (int i = 0; i < K_; i++) tr[i] = trans[i * K_ + lane];
        score = start_t[lane] + em[lane];
    } else {
#pragma unroll
        for (int i = 0; i < K_; i++) tr[i] = 0.f;
        score = -3.0e38f;
    }
    __syncwarp();

    for (int t = 1; t < T_; t++) {
        float em_t = act ? em[t * K_ + lane] : 0.f;
        float m = -3.0e38f; int arg = 0;
#pragma unroll
        for (int i = 0; i < K_; i++) {
            float si = __shfl_sync(0xffffffffu, score, i);
            float v = si + tr[i];
            if (v > m) { m = v; arg = i; }   // strict > keeps first max (jnp.argmax)
        }
        if (act) {
            bp[warp][t * K_ + lane] = (unsigned char)arg;
            score = m + em_t;
        }
    }
    if (act) score += end_t[lane];

    int best = 0; float bm = -3.0e38f;
#pragma unroll
    for (int jj = 0; jj < K_; jj++) {
        float sj = __shfl_sync(0xffffffffu, score, jj);
        if (sj > bm) { bm = sj; best = jj; }
    }
    __syncwarp();
    if (lane == 0) {
        int tag = best;
        out[b * T_ + (T_ - 1)] = (float)tag;
        for (int t = T_ - 2; t >= 0; t--) {
            tag = bp[warp][(t + 1) * K_ + tag];
            out[b * T_ + t] = (float)tag;
        }
    }
}

// ---------------- launch -------------------------------------------------------
extern "C" void kernel_launch(void* const* d_in, const int* in_sizes, int n_in,
                              void* d_out, int out_size)
{
    const int*   x      = (const int*)  d_in[0];
    const float* emb    = (const float*)d_in[1];
    const float* w_ih_f = (const float*)d_in[2];
    const float* w_hh_f = (const float*)d_in[3];
    const float* b_ih_f = (const float*)d_in[4];
    const float* b_hh_f = (const float*)d_in[5];
    const float* w_ih_b = (const float*)d_in[6];
    const float* w_hh_b = (const float*)d_in[7];
    const float* b_ih_b = (const float*)d_in[8];
    const float* b_hh_b = (const float*)d_in[9];
    const float* W_tag  = (const float*)d_in[10];
    const float* b_tag  = (const float*)d_in[11];
    const float* start_t= (const float*)d_in[12];
    const float* end_t  = (const float*)d_in[13];
    const float* trans  = (const float*)d_in[14];
    float* out = (float*)d_out;

    proj_kernel<<<dim3(16, 1024), 256>>>(x, emb, w_ih_f, w_ih_b,
                                         b_ih_f, b_hh_f, b_ih_b, b_hh_b);
    lstm_kernel<<<128, 512>>>(w_hh_f, w_hh_b);
    emis_kernel<<<8192, 256>>>(W_tag, b_tag);
    viterbi_kernel<<<64, 64>>>(start_t, end_t, trans, out);
}

// round 13
// speedup vs baseline: 1.9104x; 1.0194x over previous
#include <cuda_runtime.h>
#include <math.h>
#include <stdint.h>

#define T_   512
#define B_   128
#define E_   128
#define HD_  128
#define G4_  512   // 4*HD
#define K_   9
#define V_   50000

typedef unsigned long long ull;

// ---------------- f32x2 packed-math helpers (FFMA2 — PTX-only on sm_103a) -----
__device__ __forceinline__ void fma2(ull& d, ull a, ull b) {
    asm("fma.rn.f32x2 %0, %1, %2, %0;" : "+l"(d) : "l"(a), "l"(b));
}
__device__ __forceinline__ ull dup2(float x) {
    ull r;
    asm("mov.b64 %0, {%1, %1};" : "=l"(r) : "f"(x));
    return r;
}
__device__ __forceinline__ float2 unpack2(ull v) {
    float2 f;
    asm("mov.b64 {%0, %1}, %2;" : "=f"(f.x), "=f"(f.y) : "l"(v));
    return f;
}

// ---------------- scratch (device globals; no runtime allocation) -------------
__device__ float g_Xf[(size_t)T_ * B_ * G4_];   // [t][b][512] fwd input proj + bias
__device__ float g_Xb[(size_t)T_ * B_ * G4_];   // backward
__device__ float g_H [(size_t)T_ * B_ * 256];   // [t][b][256] concat hidden
__device__ float g_emis[(size_t)B_ * T_ * K_];  // [b][t][k]

// tiny no-op spacers: shift lstm to the 4th launch slot (ncu captures launch #4)
__global__ void nop_kernel() {}

// ---------------- kernel A: embed gather + input projection GEMM --------------
__global__ void __launch_bounds__(256) proj_kernel(
                            const int* __restrict__ x, const float* __restrict__ emb,
                            const float* __restrict__ w_f, const float* __restrict__ w_b,
                            const float* __restrict__ bihf, const float* __restrict__ bhhf,
                            const float* __restrict__ bihb, const float* __restrict__ bhhb)
{
    __shared__ float As[64][72];      // [k][row], 72-pad keeps 16B row alignment
    __shared__ float Bs[64][72];      // [k][col]
    __shared__ float bias_s[64];
    __shared__ int   tok_s[64];

    const int tid = threadIdx.x;
    const int m0 = blockIdx.y * 64;
    const int n0 = blockIdx.x * 64;           // 0..1023
    const int dir = n0 >> 9;
    const int gbase = n0 & 511;
    const float* w  = dir ? w_b  : w_f;
    const float* bi = dir ? bihb : bihf;
    const float* bh = dir ? bhhb : bhhf;

    if (tid < 64) {
        int m = m0 + tid;
        int t = m >> 7, b = m & 127;
        int tok = x[b * T_ + t];
        if ((unsigned)tok >= (unsigned)V_) tok = 0;   // safety clamp
        tok_s[tid] = tok;
        int grow = gbase + tid;
        bias_s[tid] = bi[grow] + bh[grow];
    }
    __syncthreads();

    const int tx = tid & 15, ty = tid >> 4;
    ull acc[4][2];
#pragma unroll
    for (int i = 0; i < 4; i++) { acc[i][0] = 0ull; acc[i][1] = 0ull; }

    for (int kc = 0; kc < 128; kc += 64) {
        for (int idx = tid; idx < 4096; idx += 256) {
            int row = idx >> 6, kk = idx & 63;
            As[kk][row] = emb[(size_t)tok_s[row] * E_ + kc + kk];
            Bs[kk][row] = w[(size_t)(gbase + row) * E_ + kc + kk];
        }
        __syncthreads();

#pragma unroll 8
        for (int k = 0; k < 64; k++) {
            float4     av = *(const float4*)&As[k][ty * 4];
            ulonglong2 bv = *(const ulonglong2*)&Bs[k][tx * 4];
            ull a0 = dup2(av.x), a1 = dup2(av.y), a2 = dup2(av.z), a3 = dup2(av.w);
            fma2(acc[0][0], a0, bv.x); fma2(acc[0][1], a0, bv.y);
            fma2(acc[1][0], a1, bv.x); fma2(acc[1][1], a1, bv.y);
            fma2(acc[2][0], a2, bv.x); fma2(acc[2][1], a2, bv.y);
            fma2(acc[3][0], a3, bv.x); fma2(acc[3][1], a3, bv.y);
        }
        __syncthreads();
    }

    float* X = dir ? g_Xb : g_Xf;
    const int col = tx * 4;
#pragma unroll
    for (int i = 0; i < 4; i++) {
        int m = m0 + ty * 4 + i;
        float2 c01 = unpack2(acc[i][0]);
        float2 c23 = unpack2(acc[i][1]);
        float4 o = make_float4(c01.x + bias_s[col + 0], c01.y + bias_s[col + 1],
                               c23.x + bias_s[col + 2], c23.y + bias_s[col + 3]);
        *(float4*)&X[(size_t)m * G4_ + gbase + col] = o;
    }
}

// ---------------- kernel B: cluster-of-4 LSTM, 4-way k-split ------------------
// 128 CTAs = 32 clusters of 4. CTA: 512 threads = 128 rows x 4 k-quarters;
// each thread: wreg[32], all 8 batches (4 FFMA2 per mov). h via DSMEM double
// buffer; sync via mbarrier (release-arrive is cumulative past __syncthreads).
__global__ void __cluster_dims__(4, 1, 1) __launch_bounds__(512, 1)
lstm_kernel(const float* __restrict__ whhf, const float* __restrict__ whhb)
{
    __shared__ __align__(16) float hkb[2][HD_ * 8];   // [parity][k][b] 8KB
    __shared__ float gq[4][8][128];                   // [kq][b][row] 16KB
    __shared__ __align__(8) unsigned long long mbar[2];

    const int tid = threadIdx.x;                      // 512 threads
    uint32_t rank;
    asm("mov.u32 %0, %%cluster_ctarank;" : "=r"(rank));
    const int cid = blockIdx.x >> 2;                  // 0..31
    const int dir = cid >> 4;
    const int b0  = (cid & 15) * 8;

    const float* Xin = dir ? g_Xb : g_Xf;
    const float* whh = dir ? whhb : whhf;

    // GEMM role: local row r, k-quarter kq
    const int r  = tid & 127;
    const int kq = tid >> 7;
    const int grow = (r >> 5) * 128 + (int)rank * 32 + (r & 31);

    float wreg[32];
#pragma unroll
    for (int k = 0; k < 32; k += 4) {
        float4 v = *(const float4*)&whh[(size_t)grow * HD_ + kq * 32 + k];
        wreg[k] = v.x; wreg[k + 1] = v.y; wreg[k + 2] = v.z; wreg[k + 3] = v.w;
    }

    // ACT role (threads 0..255): unit uu, batch bact
    const int uu = tid & 31, bact = (tid >> 5) & 7;
    const int ug = (int)rank * 32 + uu;
    const bool is_act = (tid < 256);

    if (tid == 0) {
        uint32_t mb = (uint32_t)__cvta_generic_to_shared(&mbar[0]);
        asm volatile("mbarrier.init.shared.b64 [%0], 4;" :: "r"(mb) : "memory");
        asm volatile("mbarrier.init.shared.b64 [%0], 4;" :: "r"(mb + 8) : "memory");
    }
    for (int i = tid; i < HD_ * 8; i += 512) hkb[0][i] = 0.f;
    float c = 0.f;
    int ph0 = 0, ph1 = 0;
    __syncthreads();
    // cluster rally: all mbarriers initialized before any remote arrive
    asm volatile("barrier.cluster.arrive.aligned;" ::: "memory");
    asm volatile("barrier.cluster.wait.aligned;"   ::: "memory");

    const uint32_t mb_base = (uint32_t)__cvta_generic_to_shared(&mbar[0]);
    const uint32_t h_off0  = is_act
        ? (uint32_t)__cvta_generic_to_shared(&hkb[0][ug * 8 + bact]) : 0u;

    for (int s = 0; s < T_; s++) {
        const int t = dir ? (T_ - 1 - s) : s;

        // X prefetch BEFORE the wait (global, h-independent -> overlaps sync)
        float x0 = 0.f, x1 = 0.f, x2 = 0.f, x3 = 0.f;
        if (is_act) {
            const float* Xr = &Xin[(size_t)t * B_ * G4_ + (size_t)(b0 + bact) * G4_];
            x0 = Xr[ug]; x1 = Xr[128 + ug]; x2 = Xr[256 + ug]; x3 = Xr[384 + ug];
        }

        // wait until h buffer (s&1) is full in MY smem (acquire, cluster scope)
        if (s > 0) {
            const uint32_t mb = mb_base + (uint32_t)(s & 1) * 8u;
            const int par = (s & 1) ? ph1 : ph0;
            uint32_t done;
            asm volatile(
                "{\n\t.reg .pred p;\n\t"
                "mbarrier.try_wait.parity.acquire.cluster.shared::cta.b64 p, [%1], %2;\n\t"
                "selp.b32 %0, 1, 0, p;\n\t}"
                : "=r"(done) : "r"(mb), "r"(par) : "memory");
            if (!done) {
                asm volatile(
                    "{\n\t.reg .pred P1;\n\t"
                    "WL_%=:\n\t"
                    "mbarrier.try_wait.parity.acquire.cluster.shared::cta.b64 P1, [%0], %1, 0x989680;\n\t"
                    "@P1 bra.uni WD_%=;\n\t"
                    "bra.uni WL_%=;\n\t"
                    "WD_%=:\n\t}"
                    :: "r"(mb), "r"(par) : "memory");
            }
            if (s & 1) ph1 ^= 1; else ph0 ^= 1;
        }

        // GEMM partial over my k-quarter: all 8 batches per thread
        const float* hk = hkb[s & 1] + kq * 32 * 8;
        ull a01 = 0ull, a23 = 0ull, a45 = 0ull, a67 = 0ull;
#pragma unroll
        for (int k = 0; k < 32; k++) {
            ulonglong2 hp0 = *(const ulonglong2*)&hk[k * 8];
            ulonglong2 hp1 = *(const ulonglong2*)&hk[k * 8 + 4];
            ull wd = dup2(wreg[k]);
            fma2(a01, wd, hp0.x);
            fma2(a23, wd, hp0.y);
            fma2(a45, wd, hp1.x);
            fma2(a67, wd, hp1.y);
        }
        {
            float2 p01 = unpack2(a01), p23 = unpack2(a23);
            float2 p45 = unpack2(a45), p67 = unpack2(a67);
            gq[kq][0][r] = p01.x; gq[kq][1][r] = p01.y;
            gq[kq][2][r] = p23.x; gq[kq][3][r] = p23.y;
            gq[kq][4][r] = p45.x; gq[kq][5][r] = p45.y;
            gq[kq][6][r] = p67.x; gq[kq][7][r] = p67.y;
        }
        __syncthreads();

        // activation + h broadcast
        if (is_act) {
            float pi = (gq[0][bact][uu]      + gq[1][bact][uu])
                     + (gq[2][bact][uu]      + gq[3][bact][uu])      + x0;
            float pf = (gq[0][bact][32 + uu] + gq[1][bact][32 + uu])
                     + (gq[2][bact][32 + uu] + gq[3][bact][32 + uu]) + x1;
            float pg = (gq[0][bact][64 + uu] + gq[1][bact][64 + uu])
                     + (gq[2][bact][64 + uu] + gq[3][bact][64 + uu]) + x2;
            float po = (gq[0][bact][96 + uu] + gq[1][bact][96 + uu])
                     + (gq[2][bact][96 + uu] + gq[3][bact][96 + uu]) + x3;
            float ig = 1.f / (1.f + expf(-pi));
            float fg = 1.f / (1.f + expf(-pf));
            float gg = tanhf(pg);
            float og = 1.f / (1.f + expf(-po));
            c = fg * c + ig * gg;
            float h = og * tanhf(c);

            if (s < T_ - 1) {
                const uint32_t off = h_off0 + (uint32_t)((s + 1) & 1) * (HD_ * 8 * 4);
#pragma unroll
                for (int ctac = 0; ctac < 4; ctac++) {
                    uint32_t rem;
                    asm("mapa.shared::cluster.u32 %0, %1, %2;" : "=r"(rem) : "r"(off), "r"(ctac));
                    asm volatile("st.shared::cluster.f32 [%0], %1;" :: "r"(rem), "f"(h) : "memory");
                }
            }
            g_H[(size_t)t * B_ * 256 + (size_t)(b0 + bact) * 256 + dir * 128 + ug] = h;
        }
        __syncthreads();   // all stores issued CTA-wide; protects gq reuse

        // publish: one release-arrive per destination CTA (count=4 per barrier).
        // arrive.release at cluster scope is cumulative past the __syncthreads,
        // ordering every thread's DSMEM h-stores (standard producer pattern).
        if (s < T_ - 1 && tid < 4) {
            const uint32_t loc = mb_base + (uint32_t)((s + 1) & 1) * 8u;
            uint32_t rem;
            asm("mapa.shared::cluster.u32 %0, %1, %2;" : "=r"(rem) : "r"(loc), "r"(tid));
            asm volatile("mbarrier.arrive.release.cluster.shared::cluster.b64 _, [%0];"
                         :: "r"(rem) : "memory");
        }
    }

    // final rally: no CTA exits while peers might still touch its SMEM
    asm volatile("barrier.cluster.arrive.aligned;" ::: "memory");
    asm volatile("barrier.cluster.wait.aligned;"   ::: "memory");
}

// ---------------- kernel C: emissions = H @ W_tag.T + b_tag -------------------
__global__ void emis_kernel(const float* __restrict__ W_tag, const float* __restrict__ b_tag)
{
    __shared__ float Ws[K_ * 256];
    __shared__ float bs[K_];
    const int tid = threadIdx.x;
    for (int i = tid; i < K_ * 256; i += 256) Ws[i] = W_tag[i];
    if (tid < K_) bs[tid] = b_tag[tid];
    __syncthreads();

    const int warp = tid >> 5, lane = tid & 31;
    const int rr = blockIdx.x * 8 + warp;          // row in [t*128+b]
    const float* hrow = &g_H[(size_t)rr * 256];
    float hv[8];
#pragma unroll
    for (int i = 0; i < 8; i++) hv[i] = hrow[lane + 32 * i];
    const int t = rr >> 7, b = rr & 127;
#pragma unroll
    for (int k = 0; k < K_; k++) {
        float s = 0.f;
#pragma unroll
        for (int i = 0; i < 8; i++) s += hv[i] * Ws[k * 256 + lane + 32 * i];
#pragma unroll
        for (int off = 16; off > 0; off >>= 1) s += __shfl_down_sync(0xffffffffu, s, off);
        if (lane == 0) g_emis[(size_t)b * T_ * K_ + t * K_ + k] = s + bs[k];
    }
}

// ---------------- kernel D: CRF Viterbi — SMEM-staged emissions ---------------
__global__ void __launch_bounds__(64) viterbi_kernel(
                               const float* __restrict__ start_t, const float* __restrict__ end_t,
                               const float* __restrict__ trans, float* __restrict__ out)
{
    __shared__ float em_s[2][T_ * K_];          // 36864 B
    __shared__ unsigned char bp[2][T_ * K_];    //  9216 B
    const int tid = threadIdx.x, warp = tid >> 5, lane = tid & 31;
    const int b = blockIdx.x * 2 + warp;

    {
        const float4* src = (const float4*)&g_emis[(size_t)b * T_ * K_];
        float4* dst = (float4*)em_s[warp];
        for (int i = lane; i < (T_ * K_) / 4; i += 32) dst[i] = src[i];
    }
    __syncwarp();

    const float* em = em_s[warp];
    const bool act = (lane < K_);

    float tr[K_];
    float score;
    if (act) {
#pragma unroll
        for (int i = 0; i < K_; i++) tr[i] = trans[i * K_ + lane];
        score = start_t[lane] + em[lane];
    } else {
#pragma unroll
        for (int i = 0; i < K_; i++) tr[i] = 0.f;
        score = -3.0e38f;
    }
    __syncwarp();

    for (int t = 1; t < T_; t++) {
        float em_t = act ? em[t * K_ + lane] : 0.f;
        float m = -3.0e38f; int arg = 0;
#pragma unroll
        for (int i = 0; i < K_; i++) {
            float si = __shfl_sync(0xffffffffu, score, i);
            float v = si + tr[i];
            if (v > m) { m = v; arg = i; }   // strict > keeps first max (jnp.argmax)
        }
        if (act) {
            bp[warp][t * K_ + lane] = (unsigned char)arg;
            score = m + em_t;
        }
    }
    if (act) score += end_t[lane];

    int best = 0; float bm = -3.0e38f;
#pragma unroll
    for (int jj = 0; jj < K_; jj++) {
        float sj = __shfl_sync(0xffffffffu, score, jj);
        if (sj > bm) { bm = sj; best = jj; }
    }
    __syncwarp();
    if (lane == 0) {
        int tag = best;
        out[b * T_ + (T_ - 1)] = (float)tag;
        for (int t = T_ - 2; t >= 0; t--) {
            tag = bp[warp][(t + 1) * K_ + tag];
            out[b * T_ + t] = (float)tag;
        }
    }
}

// ---------------- launch -------------------------------------------------------
extern "C" void kernel_launch(void* const* d_in, const int* in_sizes, int n_in,
                              void* d_out, int out_size)
{
    const int*   x      = (const int*)  d_in[0];
    const float* emb    = (const float*)d_in[1];
    const float* w_ih_f = (const float*)d_in[2];
    const float* w_hh_f = (const float*)d_in[3];
    const float* b_ih_f = (const float*)d_in[4];
    const float* b_hh_f = (const float*)d_in[5];
    const float* w_ih_b = (const float*)d_in[6];
    const float* w_hh_b = (const float*)d_in[7];
    const float* b_ih_b = (const float*)d_in[8];
    const float* b_hh_b = (const float*)d_in[9];
    const float* W_tag  = (const float*)d_in[10];
    const float* b_tag  = (const float*)d_in[11];
    const float* start_t= (const float*)d_in[12];
    const float* end_t  = (const float*)d_in[13];
    const float* trans  = (const float*)d_in[14];
    float* out = (float*)d_out;

    proj_kernel<<<dim3(16, 1024), 256>>>(x, emb, w_ih_f, w_ih_b,
                                         b_ih_f, b_hh_f, b_ih_b, b_hh_b);
    nop_kernel<<<1, 32>>>();                       // spacer: lstm -> launch #4
    nop_kernel<<<1, 32>>>();                       // (ncu captures launch #4)
    lstm_kernel<<<128, 512>>>(w_hh_f, w_hh_b);
    emis_kernel<<<8192, 256>>>(W_tag, b_tag);
    viterbi_kernel<<<64, 64>>>(start_t, end_t, trans, out);
}

// round 14
// speedup vs baseline: 2.1987x; 1.1509x over previous
#include <cuda_runtime.h>
#include <math.h>
#include <stdint.h>

#define T_   512
#define B_   128
#define E_   128
#define HD_  128
#define G4_  512   // 4*HD
#define K_   9
#define V_   50000

typedef unsigned long long ull;

// ---------------- f32x2 packed-math helpers (FFMA2 — PTX-only on sm_103a) -----
__device__ __forceinline__ void fma2(ull& d, ull a, ull b) {
    asm("fma.rn.f32x2 %0, %1, %2, %0;" : "+l"(d) : "l"(a), "l"(b));
}
__device__ __forceinline__ ull dup2(float x) {
    ull r;
    asm("mov.b64 %0, {%1, %1};" : "=l"(r) : "f"(x));
    return r;
}
__device__ __forceinline__ float2 unpack2(ull v) {
    float2 f;
    asm("mov.b64 {%0, %1}, %2;" : "=f"(f.x), "=f"(f.y) : "l"(v));
    return f;
}

// ---------------- scratch (device globals; no runtime allocation) -------------
__device__ float g_Xf[(size_t)T_ * B_ * G4_];   // [t][b][512] fwd input proj + bias
__device__ float g_Xb[(size_t)T_ * B_ * G4_];   // backward
__device__ float g_H [(size_t)T_ * B_ * 256];   // [t][b][256] concat hidden
__device__ float g_emis[(size_t)B_ * T_ * K_];  // [b][t][k]

// tiny no-op spacers: keep lstm on the 4th launch slot (ncu captures launch #4)
__global__ void nop_kernel() {}

// ---------------- kernel A: embed gather + input projection GEMM --------------
__global__ void __launch_bounds__(256) proj_kernel(
                            const int* __restrict__ x, const float* __restrict__ emb,
                            const float* __restrict__ w_f, const float* __restrict__ w_b,
                            const float* __restrict__ bihf, const float* __restrict__ bhhf,
                            const float* __restrict__ bihb, const float* __restrict__ bhhb)
{
    __shared__ float As[64][72];      // [k][row], 72-pad keeps 16B row alignment
    __shared__ float Bs[64][72];      // [k][col]
    __shared__ float bias_s[64];
    __shared__ int   tok_s[64];

    const int tid = threadIdx.x;
    const int m0 = blockIdx.y * 64;
    const int n0 = blockIdx.x * 64;           // 0..1023
    const int dir = n0 >> 9;
    const int gbase = n0 & 511;
    const float* w  = dir ? w_b  : w_f;
    const float* bi = dir ? bihb : bihf;
    const float* bh = dir ? bhhb : bhhf;

    if (tid < 64) {
        int m = m0 + tid;
        int t = m >> 7, b = m & 127;
        int tok = x[b * T_ + t];
        if ((unsigned)tok >= (unsigned)V_) tok = 0;   // safety clamp
        tok_s[tid] = tok;
        int grow = gbase + tid;
        bias_s[tid] = bi[grow] + bh[grow];
    }
    __syncthreads();

    const int tx = tid & 15, ty = tid >> 4;
    ull acc[4][2];
#pragma unroll
    for (int i = 0; i < 4; i++) { acc[i][0] = 0ull; acc[i][1] = 0ull; }

    for (int kc = 0; kc < 128; kc += 64) {
        for (int idx = tid; idx < 4096; idx += 256) {
            int row = idx >> 6, kk = idx & 63;
            As[kk][row] = emb[(size_t)tok_s[row] * E_ + kc + kk];
            Bs[kk][row] = w[(size_t)(gbase + row) * E_ + kc + kk];
        }
        __syncthreads();

#pragma unroll 8
        for (int k = 0; k < 64; k++) {
            float4     av = *(const float4*)&As[k][ty * 4];
            ulonglong2 bv = *(const ulonglong2*)&Bs[k][tx * 4];
            ull a0 = dup2(av.x), a1 = dup2(av.y), a2 = dup2(av.z), a3 = dup2(av.w);
            fma2(acc[0][0], a0, bv.x); fma2(acc[0][1], a0, bv.y);
            fma2(acc[1][0], a1, bv.x); fma2(acc[1][1], a1, bv.y);
            fma2(acc[2][0], a2, bv.x); fma2(acc[2][1], a2, bv.y);
            fma2(acc[3][0], a3, bv.x); fma2(acc[3][1], a3, bv.y);
        }
        __syncthreads();
    }

    float* X = dir ? g_Xb : g_Xf;
    const int col = tx * 4;
#pragma unroll
    for (int i = 0; i < 4; i++) {
        int m = m0 + ty * 4 + i;
        float2 c01 = unpack2(acc[i][0]);
        float2 c23 = unpack2(acc[i][1]);
        float4 o = make_float4(c01.x + bias_s[col + 0], c01.y + bias_s[col + 1],
                               c23.x + bias_s[col + 2], c23.y + bias_s[col + 3]);
        *(float4*)&X[(size_t)m * G4_ + gbase + col] = o;
    }
}

// ---------------- kernel B: cluster-of-2 LSTM ---------------------------------
// 128 CTAs = 64 clusters of 2: cluster = (dir, batch-group of 4); rank = unit
// half (64 units). CTA: 512 threads = 256 gate rows x 2 k-halves; each thread
// wreg[64] x 4 batches. Activation fully local to the CTA that owns the unit's
// 4 gate rows; only the h value crosses CTAs (1 remote DSMEM store/item).
__global__ void __cluster_dims__(2, 1, 1) __launch_bounds__(512, 1)
lstm_kernel(const float* __restrict__ whhf, const float* __restrict__ whhb)
{
    __shared__ __align__(16) float hkb[2][HD_ * 4];   // [parity][k][b] 4KB
    __shared__ float gh[2][4][256];                   // [khalf][b][row] 8KB
    __shared__ __align__(8) unsigned long long mbar[2];

    const int tid = threadIdx.x;                      // 512 threads
    uint32_t rank;
    asm("mov.u32 %0, %%cluster_ctarank;" : "=r"(rank));
    const int cid = blockIdx.x >> 1;                  // 0..63
    const int dir = cid >> 5;
    const int b0  = (cid & 31) * 4;

    const float* Xin = dir ? g_Xb : g_Xf;
    const float* whh = dir ? whhb : whhf;

    // GEMM role: local row r (0..255) = gate(2b)<<6 | unit-in-half, k-half
    const int r    = tid & 255;
    const int half = tid >> 8;
    const int grow = (r >> 6) * 128 + (int)rank * 64 + (r & 63);

    float wreg[64];
#pragma unroll
    for (int k = 0; k < 64; k += 4) {
        float4 v = *(const float4*)&whh[(size_t)grow * HD_ + half * 64 + k];
        wreg[k] = v.x; wreg[k + 1] = v.y; wreg[k + 2] = v.z; wreg[k + 3] = v.w;
    }

    // ACT role (threads 0..255): batch b (0..3), unit-in-half ul (0..63)
    const int bact = tid >> 6, ul = tid & 63;
    const int ug = (int)rank * 64 + ul;               // global unit 0..127
    const bool is_act = (tid < 256);

    if (tid == 0) {
        uint32_t mb = (uint32_t)__cvta_generic_to_shared(&mbar[0]);
        asm volatile("mbarrier.init.shared.b64 [%0], 2;" :: "r"(mb) : "memory");
        asm volatile("mbarrier.init.shared.b64 [%0], 2;" :: "r"(mb + 8) : "memory");
    }
    for (int i = tid; i < HD_ * 4; i += 512) hkb[0][i] = 0.f;
    float c = 0.f;
    int ph0 = 0, ph1 = 0;
    __syncthreads();
    // cluster rally: all mbarriers initialized before any remote arrive
    asm volatile("barrier.cluster.arrive.aligned;" ::: "memory");
    asm volatile("barrier.cluster.wait.aligned;"   ::: "memory");

    const uint32_t mb_base = (uint32_t)__cvta_generic_to_shared(&mbar[0]);
    const uint32_t h_off0  = is_act
        ? (uint32_t)__cvta_generic_to_shared(&hkb[0][ug * 4 + bact]) : 0u;

    for (int s = 0; s < T_; s++) {
        const int t = dir ? (T_ - 1 - s) : s;

        // X prefetch BEFORE the wait (global, h-independent -> overlaps sync)
        float x0 = 0.f, x1 = 0.f, x2 = 0.f, x3 = 0.f;
        if (is_act) {
            const float* Xr = &Xin[(size_t)t * B_ * G4_ + (size_t)(b0 + bact) * G4_];
            x0 = Xr[ug]; x1 = Xr[128 + ug]; x2 = Xr[256 + ug]; x3 = Xr[384 + ug];
        }

        // wait until h buffer (s&1) is full in MY smem (acquire, cluster scope)
        if (s > 0) {
            const uint32_t mb = mb_base + (uint32_t)(s & 1) * 8u;
            const int par = (s & 1) ? ph1 : ph0;
            uint32_t done;
            asm volatile(
                "{\n\t.reg .pred p;\n\t"
                "mbarrier.try_wait.parity.acquire.cluster.shared::cta.b64 p, [%1], %2;\n\t"
                "selp.b32 %0, 1, 0, p;\n\t}"
                : "=r"(done) : "r"(mb), "r"(par) : "memory");
            if (!done) {
                asm volatile(
                    "{\n\t.reg .pred P1;\n\t"
                    "WL_%=:\n\t"
                    "mbarrier.try_wait.parity.acquire.cluster.shared::cta.b64 P1, [%0], %1, 0x989680;\n\t"
                    "@P1 bra.uni WD_%=;\n\t"
                    "bra.uni WL_%=;\n\t"
                    "WD_%=:\n\t}"
                    :: "r"(mb), "r"(par) : "memory");
            }
            if (s & 1) ph1 ^= 1; else ph0 ^= 1;
        }

        // GEMM partial over my k-half (h broadcast LDS.128, W in regs)
        const float* hk = hkb[s & 1] + half * 64 * 4;
        ull a01 = 0ull, a23 = 0ull;
#pragma unroll
        for (int k = 0; k < 64; k++) {
            ulonglong2 hp = *(const ulonglong2*)&hk[k * 4];
            ull wd = dup2(wreg[k]);
            fma2(a01, wd, hp.x);
            fma2(a23, wd, hp.y);
        }
        {
            float2 p01 = unpack2(a01), p23 = unpack2(a23);
            gh[half][0][r] = p01.x;
            gh[half][1][r] = p01.y;
            gh[half][2][r] = p23.x;
            gh[half][3][r] = p23.y;
        }
        __syncthreads();

        // activation + h store (local unit: gate rows live in THIS CTA)
        if (is_act) {
            float pi = gh[0][bact][ul]       + gh[1][bact][ul]       + x0;
            float pf = gh[0][bact][64 + ul]  + gh[1][bact][64 + ul]  + x1;
            float pg = gh[0][bact][128 + ul] + gh[1][bact][128 + ul] + x2;
            float po = gh[0][bact][192 + ul] + gh[1][bact][192 + ul] + x3;
            float ig = 1.f / (1.f + expf(-pi));
            float fg = 1.f / (1.f + expf(-pf));
            float gg = tanhf(pg);
            float og = 1.f / (1.f + expf(-po));
            c = fg * c + ig * gg;
            float h = og * tanhf(c);

            if (s < T_ - 1) {
                const uint32_t off = h_off0 + (uint32_t)((s + 1) & 1) * (HD_ * 4 * 4);
#pragma unroll
                for (int ctac = 0; ctac < 2; ctac++) {
                    uint32_t rem;
                    asm("mapa.shared::cluster.u32 %0, %1, %2;" : "=r"(rem) : "r"(off), "r"(ctac));
                    asm volatile("st.shared::cluster.f32 [%0], %1;" :: "r"(rem), "f"(h) : "memory");
                }
            }
            g_H[(size_t)t * B_ * 256 + (size_t)(b0 + bact) * 256 + dir * 128 + ug] = h;
        }
        __syncthreads();   // all stores issued CTA-wide; protects gh reuse

        // publish: one release-arrive per destination CTA (count=2 per barrier).
        // arrive.release at cluster scope is cumulative past the __syncthreads.
        if (s < T_ - 1 && tid < 2) {
            const uint32_t loc = mb_base + (uint32_t)((s + 1) & 1) * 8u;
            uint32_t rem;
            asm("mapa.shared::cluster.u32 %0, %1, %2;" : "=r"(rem) : "r"(loc), "r"(tid));
            asm volatile("mbarrier.arrive.release.cluster.shared::cluster.b64 _, [%0];"
                         :: "r"(rem) : "memory");
        }
    }

    // final rally: no CTA exits while its peer might still touch its SMEM
    asm volatile("barrier.cluster.arrive.aligned;" ::: "memory");
    asm volatile("barrier.cluster.wait.aligned;"   ::: "memory");
}

// ---------------- kernel C: emissions = H @ W_tag.T + b_tag -------------------
__global__ void emis_kernel(const float* __restrict__ W_tag, const float* __restrict__ b_tag)
{
    __shared__ float Ws[K_ * 256];
    __shared__ float bs[K_];
    const int tid = threadIdx.x;
    for (int i = tid; i < K_ * 256; i += 256) Ws[i] = W_tag[i];
    if (tid < K_) bs[tid] = b_tag[tid];
    __syncthreads();

    const int warp = tid >> 5, lane = tid & 31;
    const int rr = blockIdx.x * 8 + warp;          // row in [t*128+b]
    const float* hrow = &g_H[(size_t)rr * 256];
    float hv[8];
#pragma unroll
    for (int i = 0; i < 8; i++) hv[i] = hrow[lane + 32 * i];
    const int t = rr >> 7, b = rr & 127;
#pragma unroll
    for (int k = 0; k < K_; k++) {
        float s = 0.f;
#pragma unroll
        for (int i = 0; i < 8; i++) s += hv[i] * Ws[k * 256 + lane + 32 * i];
#pragma unroll
        for (int off = 16; off > 0; off >>= 1) s += __shfl_down_sync(0xffffffffu, s, off);
        if (lane == 0) g_emis[(size_t)b * T_ * K_ + t * K_ + k] = s + bs[k];
    }
}

// ---------------- kernel D: CRF Viterbi — SMEM-staged emissions ---------------
__global__ void __launch_bounds__(64) viterbi_kernel(
                               const float* __restrict__ start_t, const float* __restrict__ end_t,
                               const float* __restrict__ trans, float* __restrict__ out)
{
    __shared__ float em_s[2][T_ * K_];          // 36864 B
    __shared__ unsigned char bp[2][T_ * K_];    //  9216 B
    const int tid = threadIdx.x, warp = tid >> 5, lane = tid & 31;
    const int b = blockIdx.x * 2 + warp;

    {
        const float4* src = (const float4*)&g_emis[(size_t)b * T_ * K_];
        float4* dst = (float4*)em_s[warp];
        for (int i = lane; i < (T_ * K_) / 4; i += 32) dst[i] = src[i];
    }
    __syncwarp();

    const float* em = em_s[warp];
    const bool act = (lane < K_);

    float tr[K_];
    float score;
    if (act) {
#pragma unroll
        for (int i = 0; i < K_; i++) tr[i] = trans[i * K_ + lane];
        score = start_t[lane] + em[lane];
    } else {
#pragma unroll
        for (int i = 0; i < K_; i++) tr[i] = 0.f;
        score = -3.0e38f;
    }
    __syncwarp();

    for (int t = 1; t < T_; t++) {
        float em_t = act ? em[t * K_ + lane] : 0.f;
        float m = -3.0e38f; int arg = 0;
#pragma unroll
        for (int i = 0; i < K_; i++) {
            float si = __shfl_sync(0xffffffffu, score, i);
            float v = si + tr[i];
            if (v > m) { m = v; arg = i; }   // strict > keeps first max (jnp.argmax)
        }
        if (act) {
            bp[warp][t * K_ + lane] = (unsigned char)arg;
            score = m + em_t;
        }
    }
    if (act) score += end_t[lane];

    int best = 0; float bm = -3.0e38f;
#pragma unroll
    for (int jj = 0; jj < K_; jj++) {
        float sj = __shfl_sync(0xffffffffu, score, jj);
        if (sj > bm) { bm = sj; best = jj; }
    }
    __syncwarp();
    if (lane == 0) {
        int tag = best;
        out[b * T_ + (T_ - 1)] = (float)tag;
        for (int t = T_ - 2; t >= 0; t--) {
            tag = bp[warp][(t + 1) * K_ + tag];
            out[b * T_ + t] = (float)tag;
        }
    }
}

// ---------------- launch -------------------------------------------------------
extern "C" void kernel_launch(void* const* d_in, const int* in_sizes, int n_in,
                              void* d_out, int out_size)
{
    const int*   x      = (const int*)  d_in[0];
    const float* emb    = (const float*)d_in[1];
    const float* w_ih_f = (const float*)d_in[2];
    const float* w_hh_f = (const float*)d_in[3];
    const float* b_ih_f = (const float*)d_in[4];
    const float* b_hh_f = (const float*)d_in[5];
    const float* w_ih_b = (const float*)d_in[6];
    const float* w_hh_b = (const float*)d_in[7];
    const float* b_ih_b = (const float*)d_in[8];
    const float* b_hh_b = (const float*)d_in[9];
    const float* W_tag  = (const float*)d_in[10];
    const float* b_tag  = (const float*)d_in[11];
    const float* start_t= (const float*)d_in[12];
    const float* end_t  = (const float*)d_in[13];
    const float* trans  = (const float*)d_in[14];
    float* out = (float*)d_out;

    proj_kernel<<<dim3(16, 1024), 256>>>(x, emb, w_ih_f, w_ih_b,
                                         b_ih_f, b_hh_f, b_ih_b, b_hh_b);
    nop_kernel<<<1, 32>>>();                       // spacer: lstm -> launch #4
    nop_kernel<<<1, 32>>>();                       // (ncu captures launch #4)
    lstm_kernel<<<128, 512>>>(w_hh_f, w_hh_b);
    emis_kernel<<<8192, 256>>>(W_tag, b_tag);
    viterbi_kernel<<<64, 64>>>(start_t, end_t, trans, out);
}